// round 4
// baseline (speedup 1.0000x reference)
#include <cuda_runtime.h>
#include <cstdint>

#define NN 100000
#define EE 1600000
#define IN_CH 128
#define C1 256          // HEADS*HID
#define HEADS 8
#define HID 32
#define NEG 0.2f

// ---------------- scratch (static device allocations) ----------------
static __device__ float    g_xh  [(size_t)NN * C1];   // layer1 projected features
static __device__ float    g_e1s [NN * HEADS];
static __device__ float    g_e1d [NN * HEADS];
static __device__ unsigned g_m1  [NN * HEADS];        // encoded segment max
static __device__ float    g_s1  [NN * HEADS];        // softmax denominator
static __device__ float    g_acc1[(size_t)NN * C1];   // softmax numerator
static __device__ float    g_h   [(size_t)NN * C1];   // relu(layer1 out)
static __device__ float    g_h2  [NN * HID];          // layer2 projected
static __device__ float    g_e2s [NN];
static __device__ float    g_e2d [NN];
static __device__ unsigned g_m2  [NN];
static __device__ float    g_s2  [NN];
static __device__ float    g_acc2[NN * HID];
static __device__ int      g_is64;                    // edge_index dtype flag

// ---------------- helpers ----------------
__device__ __forceinline__ unsigned fenc(float f) {
    int i = __float_as_int(f);
    return (i >= 0) ? ((unsigned)i | 0x80000000u) : (unsigned)(~i);
}
__device__ __forceinline__ float fdec(unsigned u) {
    return (u & 0x80000000u) ? __int_as_float((int)(u ^ 0x80000000u))
                             : __int_as_float((int)(~u));
}
__device__ __forceinline__ float lrelu(float x) { return x > 0.f ? x : NEG * x; }

__device__ __forceinline__ void red4(float* a, float x, float y, float z, float w) {
    asm volatile("red.global.add.v4.f32 [%0], {%1,%2,%3,%4};"
                 :: "l"(a), "f"(x), "f"(y), "f"(z), "f"(w) : "memory");
}

// Load (src,dst) for edge e, handling int32 or int64 edge_index.
__device__ __forceinline__ void edge_sd(const int* __restrict__ ei, int Eo, int Et,
                                        int e, int& s, int& d) {
    if (e < Eo) {
        if (g_is64) { s = ei[2 * e]; d = ei[2 * (Eo + e)]; }
        else        { s = ei[e];     d = ei[Eo + e]; }
    } else {
        s = e - Eo; d = s;
    }
}

// ---------------- dtype probe ----------------
// int64 little-endian node ids (< 2^31) have all-zero high words; for genuine
// int32 data the odd slots are random indices — 128 consecutive zeros is
// impossible in practice.
__global__ void k_detect(const int* __restrict__ ei) {
    if (threadIdx.x == 0 && blockIdx.x == 0) {
        int all0 = 1;
        for (int i = 0; i < 128; i++)
            if (ei[2 * i + 1] != 0) { all0 = 0; break; }
        g_is64 = all0;
    }
}

// ---------------- init (zero accumulators each run) ----------------
__global__ void k_init() {
    int i = blockIdx.x * blockDim.x + threadIdx.x;
    if (i < NN * C1)    g_acc1[i] = 0.f;
    if (i < NN * HEADS) { g_m1[i] = 0u; g_s1[i] = 0.f; }
    if (i < NN * HID)   g_acc2[i] = 0.f;
    if (i < NN)         { g_m2[i] = 0u; g_s2[i] = 0.f; }
}

// ---------------- GEMM1: xh = x[N,128] @ W1[128,256] ----------------
// BM=128, BN=64, BK=16, 256 threads, 8x4 register tile.
__global__ void k_gemm1(const float* __restrict__ x, const float* __restrict__ W1) {
    __shared__ float xs[16 * 128];   // k-major: xs[k][row]
    __shared__ float ws[16 * 64];    // ws[k][col]
    int tid = threadIdx.x;
    int r0 = blockIdx.x * 128;
    int c0 = blockIdx.y * 64;
    int tx = tid & 15;      // col group (4 cols)
    int ty = tid >> 4;      // row group (8 rows)
    float acc[8][4];
#pragma unroll
    for (int i = 0; i < 8; i++)
#pragma unroll
        for (int j = 0; j < 4; j++) acc[i][j] = 0.f;

    for (int k0 = 0; k0 < 128; k0 += 16) {
#pragma unroll
        for (int i = 0; i < 2; i++) {
            int f = tid + i * 256;
            int row = f >> 2;      // 0..127
            int kq = f & 3;        // k = kq*4
            int gr = r0 + row;
            float4 v = make_float4(0.f, 0.f, 0.f, 0.f);
            if (gr < NN) v = *(const float4*)(x + (size_t)gr * 128 + k0 + kq * 4);
            xs[(kq * 4 + 0) * 128 + row] = v.x;
            xs[(kq * 4 + 1) * 128 + row] = v.y;
            xs[(kq * 4 + 2) * 128 + row] = v.z;
            xs[(kq * 4 + 3) * 128 + row] = v.w;
        }
        {
            int k = tid >> 4;      // 0..15
            int cq = tid & 15;
            float4 v = *(const float4*)(W1 + (size_t)(k0 + k) * 256 + c0 + cq * 4);
            *(float4*)(ws + k * 64 + cq * 4) = v;
        }
        __syncthreads();
#pragma unroll
        for (int kk = 0; kk < 16; kk++) {
            float4 b  = *(float4*)(ws + kk * 64 + tx * 4);
            float4 a0 = *(float4*)(xs + kk * 128 + ty * 8);
            float4 a1 = *(float4*)(xs + kk * 128 + ty * 8 + 4);
            float av[8] = {a0.x, a0.y, a0.z, a0.w, a1.x, a1.y, a1.z, a1.w};
#pragma unroll
            for (int i = 0; i < 8; i++) {
                acc[i][0] += av[i] * b.x;
                acc[i][1] += av[i] * b.y;
                acc[i][2] += av[i] * b.z;
                acc[i][3] += av[i] * b.w;
            }
        }
        __syncthreads();
    }
#pragma unroll
    for (int i = 0; i < 8; i++) {
        int gr = r0 + ty * 8 + i;
        if (gr < NN)
            *(float4*)(g_xh + (size_t)gr * 256 + c0 + tx * 4) =
                make_float4(acc[i][0], acc[i][1], acc[i][2], acc[i][3]);
    }
}

// ---------------- attention coefficients, layer 1 (warp per node) ----------------
__global__ void k_coef1(const float* __restrict__ as, const float* __restrict__ ad) {
    int w = (blockIdx.x * blockDim.x + threadIdx.x) >> 5;
    int lane = threadIdx.x & 31;
    if (w >= NN) return;
    const float4* xr = (const float4*)(g_xh + (size_t)w * 256);
    float4 v0 = xr[lane * 2], v1 = xr[lane * 2 + 1];
    const float4* a4 = (const float4*)as;
    const float4* d4 = (const float4*)ad;
    float4 s0 = a4[lane * 2], s1v = a4[lane * 2 + 1];
    float4 d0 = d4[lane * 2], d1v = d4[lane * 2 + 1];
    float ps = v0.x * s0.x + v0.y * s0.y + v0.z * s0.z + v0.w * s0.w
             + v1.x * s1v.x + v1.y * s1v.y + v1.z * s1v.z + v1.w * s1v.w;
    float pd = v0.x * d0.x + v0.y * d0.y + v0.z * d0.z + v0.w * d0.w
             + v1.x * d1v.x + v1.y * d1v.y + v1.z * d1v.z + v1.w * d1v.w;
    ps += __shfl_xor_sync(0xffffffffu, ps, 1);
    ps += __shfl_xor_sync(0xffffffffu, ps, 2);
    pd += __shfl_xor_sync(0xffffffffu, pd, 1);
    pd += __shfl_xor_sync(0xffffffffu, pd, 2);
    if ((lane & 3) == 0) {
        g_e1s[w * 8 + (lane >> 2)] = ps;
        g_e1d[w * 8 + (lane >> 2)] = pd;
    }
}

// ---------------- segment max, layer 1 (thread per edge) ----------------
__global__ void k_max1(const int* __restrict__ ei, int Eo, int Et) {
    int e = blockIdx.x * blockDim.x + threadIdx.x;
    if (e >= Et) return;
    int s, d;
    edge_sd(ei, Eo, Et, e, s, d);
    if ((unsigned)s >= NN || (unsigned)d >= NN) return;
#pragma unroll
    for (int h = 0; h < 8; h++) {
        float ev = lrelu(g_e1s[s * 8 + h] + g_e1d[d * 8 + h]);
        atomicMax(&g_m1[d * 8 + h], fenc(ev));
    }
}

// ---------------- aggregate, layer 1 (warp per edge) ----------------
__global__ void k_agg1(const int* __restrict__ ei, int Eo, int Et) {
    int w = (blockIdx.x * blockDim.x + threadIdx.x) >> 5;
    int lane = threadIdx.x & 31;
    if (w >= Et) return;
    int s, d;
    edge_sd(ei, Eo, Et, w, s, d);
    if ((unsigned)s >= NN || (unsigned)d >= NN) return;
    float p = 0.f;
    if (lane < 8) {
        float ev = lrelu(g_e1s[s * 8 + lane] + g_e1d[d * 8 + lane]);
        p = __expf(ev - fdec(g_m1[d * 8 + lane]));
        atomicAdd(&g_s1[d * 8 + lane], p);
    }
    float ph = __shfl_sync(0xffffffffu, p, lane >> 2);  // head for this lane's 8 ch
    const float4* xr = (const float4*)(g_xh + (size_t)s * 256);
    float4 v0 = xr[lane * 2], v1 = xr[lane * 2 + 1];
    float* dst = g_acc1 + (size_t)d * 256 + lane * 8;
    red4(dst,     v0.x * ph, v0.y * ph, v0.z * ph, v0.w * ph);
    red4(dst + 4, v1.x * ph, v1.y * ph, v1.z * ph, v1.w * ph);
}

// ---------------- finalize layer 1: h = relu(acc/s + b1) ----------------
__global__ void k_fin1(const float* __restrict__ b1) {
    int i = blockIdx.x * blockDim.x + threadIdx.x;
    if (i >= NN * C1) return;
    int n = i >> 8, c = i & 255;
    float v = g_acc1[i] / (g_s1[n * 8 + (c >> 5)] + 1e-16f) + b1[c];
    g_h[i] = v > 0.f ? v : 0.f;
}

// ---------------- GEMM2: h2 = h[N,256] @ W2[256,32] ----------------
// BM=64, BN=32, BK=32, 256 threads, 2x4 register tile.
__global__ void k_gemm2(const float* __restrict__ W2) {
    __shared__ float hs[32 * 64];   // k-major
    __shared__ float ws[32 * 32];
    int tid = threadIdx.x;
    int r0 = blockIdx.x * 64;
    int tx = tid & 7;       // col group of 4
    int ty = tid >> 3;      // row group of 2 (0..31)
    float acc[2][4];
#pragma unroll
    for (int i = 0; i < 2; i++)
#pragma unroll
        for (int j = 0; j < 4; j++) acc[i][j] = 0.f;

    for (int k0 = 0; k0 < 256; k0 += 32) {
#pragma unroll
        for (int i = 0; i < 2; i++) {
            int f = tid + i * 256;
            int row = f >> 3;     // 0..63
            int kq = f & 7;       // k = kq*4
            int gr = r0 + row;
            float4 v = make_float4(0.f, 0.f, 0.f, 0.f);
            if (gr < NN) v = *(const float4*)(g_h + (size_t)gr * 256 + k0 + kq * 4);
            hs[(kq * 4 + 0) * 64 + row] = v.x;
            hs[(kq * 4 + 1) * 64 + row] = v.y;
            hs[(kq * 4 + 2) * 64 + row] = v.z;
            hs[(kq * 4 + 3) * 64 + row] = v.w;
        }
        {
            int k = tid >> 3;     // 0..31
            int cq = tid & 7;
            *(float4*)(ws + k * 32 + cq * 4) =
                *(const float4*)(W2 + (size_t)(k0 + k) * 32 + cq * 4);
        }
        __syncthreads();
#pragma unroll
        for (int kk = 0; kk < 32; kk++) {
            float2 a = *(float2*)(hs + kk * 64 + ty * 2);
            float4 b = *(float4*)(ws + kk * 32 + tx * 4);
            acc[0][0] += a.x * b.x; acc[0][1] += a.x * b.y;
            acc[0][2] += a.x * b.z; acc[0][3] += a.x * b.w;
            acc[1][0] += a.y * b.x; acc[1][1] += a.y * b.y;
            acc[1][2] += a.y * b.z; acc[1][3] += a.y * b.w;
        }
        __syncthreads();
    }
#pragma unroll
    for (int i = 0; i < 2; i++) {
        int gr = r0 + ty * 2 + i;
        if (gr < NN)
            *(float4*)(g_h2 + (size_t)gr * 32 + tx * 4) =
                make_float4(acc[i][0], acc[i][1], acc[i][2], acc[i][3]);
    }
}

// ---------------- coefficients, layer 2 (thread per node) ----------------
__global__ void k_coef2(const float* __restrict__ as, const float* __restrict__ ad) {
    int n = blockIdx.x * blockDim.x + threadIdx.x;
    if (n >= NN) return;
    const float4* h4 = (const float4*)(g_h2 + (size_t)n * 32);
    float ps = 0.f, pd = 0.f;
#pragma unroll
    for (int j = 0; j < 8; j++) {
        float4 v = h4[j];
        float4 a = ((const float4*)as)[j];
        float4 b = ((const float4*)ad)[j];
        ps += v.x * a.x + v.y * a.y + v.z * a.z + v.w * a.w;
        pd += v.x * b.x + v.y * b.y + v.z * b.z + v.w * b.w;
    }
    g_e2s[n] = ps;
    g_e2d[n] = pd;
}

// ---------------- segment max, layer 2 ----------------
__global__ void k_max2(const int* __restrict__ ei, int Eo, int Et) {
    int e = blockIdx.x * blockDim.x + threadIdx.x;
    if (e >= Et) return;
    int s, d;
    edge_sd(ei, Eo, Et, e, s, d);
    if ((unsigned)s >= NN || (unsigned)d >= NN) return;
    float ev = lrelu(g_e2s[s] + g_e2d[d]);
    atomicMax(&g_m2[d], fenc(ev));
}

// ---------------- aggregate, layer 2 (8 lanes per edge) ----------------
__global__ void k_agg2(const int* __restrict__ ei, int Eo, int Et) {
    int t = blockIdx.x * blockDim.x + threadIdx.x;
    int e = t >> 3;
    int l = t & 7;
    if (e >= Et) return;
    int s, d;
    edge_sd(ei, Eo, Et, e, s, d);
    if ((unsigned)s >= NN || (unsigned)d >= NN) return;
    float ev = lrelu(g_e2s[s] + g_e2d[d]);
    float p = __expf(ev - fdec(g_m2[d]));
    if (l == 0) atomicAdd(&g_s2[d], p);
    float4 v = ((const float4*)(g_h2 + (size_t)s * 32))[l];
    red4(g_acc2 + (size_t)d * 32 + l * 4, v.x * p, v.y * p, v.z * p, v.w * p);
}

// ---------------- finalize layer 2 -> output ----------------
__global__ void k_fin2(float* __restrict__ out, const float* __restrict__ b2) {
    int i = blockIdx.x * blockDim.x + threadIdx.x;
    if (i >= NN * HID) return;
    int n = i >> 5, c = i & 31;
    out[i] = g_acc2[i] / (g_s2[n] + 1e-16f) + b2[c];
}

// ---------------- launch ----------------
extern "C" void kernel_launch(void* const* d_in, const int* in_sizes, int n_in,
                              void* d_out, int out_size) {
    const float* x   = (const float*)d_in[0];
    const int*   ei  = (const int*)d_in[1];      // int32 or int64 (probed on device)
    const float* W1  = (const float*)d_in[2];
    const float* as1 = (const float*)d_in[3];
    const float* ad1 = (const float*)d_in[4];
    const float* b1  = (const float*)d_in[5];
    const float* W2  = (const float*)d_in[6];
    const float* as2 = (const float*)d_in[7];
    const float* ad2 = (const float*)d_in[8];
    const float* b2  = (const float*)d_in[9];

    int Eo = in_sizes[1] / 2;
    if (Eo > EE) Eo = EE;
    int Et = Eo + NN;

    k_detect<<<1, 32>>>(ei);
    k_init<<<(NN * C1 + 255) / 256, 256>>>();

    dim3 g1((NN + 127) / 128, C1 / 64);
    k_gemm1<<<g1, 256>>>(x, W1);
    k_coef1<<<(NN * 32 + 255) / 256, 256>>>(as1, ad1);
    k_max1<<<(Et + 255) / 256, 256>>>(ei, Eo, Et);
    k_agg1<<<(Et + 7) / 8, 256>>>(ei, Eo, Et);          // warp per edge
    k_fin1<<<(NN * C1 + 255) / 256, 256>>>(b1);

    k_gemm2<<<(NN + 63) / 64, 256>>>(W2);
    k_coef2<<<(NN + 255) / 256, 256>>>(as2, ad2);
    k_max2<<<(Et + 255) / 256, 256>>>(ei, Eo, Et);
    k_agg2<<<(Et * 8 + 255) / 256, 256>>>(ei, Eo, Et);  // 8 lanes per edge
    k_fin2<<<(NN * HID + 255) / 256, 256>>>((float*)d_out, b2);
}

// round 5
// speedup vs baseline: 1.8970x; 1.8970x over previous
#include <cuda_runtime.h>
#include <cstdint>

#define NN 100000
#define EE 1600000
#define ETOT (EE + NN)
#define C1 256          // HEADS*HID
#define HEADS 8
#define HID 32
#define NEG 0.2f
#define SCAN_T 1024

// ---------------- scratch (static device allocations) ----------------
static __device__ float g_xh [(size_t)NN * C1];   // layer1 projected features
static __device__ float g_e1s[NN * HEADS];
static __device__ float g_e1d[NN * HEADS];
static __device__ float g_h  [(size_t)NN * C1];   // relu(layer1 out)
static __device__ float g_h2 [NN * HID];          // layer2 projected
static __device__ float g_e2s[NN];
static __device__ float g_e2d[NN];
static __device__ int   g_deg[NN];
static __device__ int   g_rowptr[NN + 1];
static __device__ int   g_cursor[NN];
static __device__ int   g_csr[ETOT];              // src ids grouped by dst
static __device__ int   g_is64;                   // edge_index dtype flag

// ---------------- helpers ----------------
__device__ __forceinline__ float lrelu(float x) { return x > 0.f ? x : NEG * x; }

__device__ __forceinline__ void edge_sd(const int* __restrict__ ei, int Eo,
                                        int e, int& s, int& d) {
    if (e < Eo) {
        if (g_is64) { s = ei[2 * e]; d = ei[2 * (Eo + e)]; }
        else        { s = ei[e];     d = ei[Eo + e]; }
    } else {
        s = e - Eo; d = s;   // self-loop
    }
}

// ---------------- dtype probe ----------------
__global__ void k_detect(const int* __restrict__ ei) {
    if (threadIdx.x == 0 && blockIdx.x == 0) {
        int all0 = 1;
        for (int i = 0; i < 128; i++)
            if (ei[2 * i + 1] != 0) { all0 = 0; break; }
        g_is64 = all0;
    }
}

// ---------------- CSR build ----------------
__global__ void k_zero() {
    int i = blockIdx.x * blockDim.x + threadIdx.x;
    if (i < NN) g_deg[i] = 0;
}

__global__ void k_hist(const int* __restrict__ ei, int Eo, int Et) {
    int e = blockIdx.x * blockDim.x + threadIdx.x;
    if (e >= Et) return;
    int s, d;
    edge_sd(ei, Eo, e, s, d);
    if ((unsigned)d >= NN) return;
    atomicAdd(&g_deg[d], 1);
}

// single-block exclusive scan of g_deg -> g_rowptr (+ copy to g_cursor)
__global__ void k_scan() {
    __shared__ int sh[SCAN_T];
    int t = threadIdx.x;
    const int CH = (NN + SCAN_T - 1) / SCAN_T;
    int lo = t * CH, hi = lo + CH; if (hi > NN) hi = NN;
    int sum = 0;
    for (int i = lo; i < hi; i++) sum += g_deg[i];
    sh[t] = sum;
    __syncthreads();
    for (int off = 1; off < SCAN_T; off <<= 1) {
        int v = (t >= off) ? sh[t - off] : 0;
        __syncthreads();
        sh[t] += v;
        __syncthreads();
    }
    int run = (t == 0) ? 0 : sh[t - 1];
    for (int i = lo; i < hi; i++) {
        int dg = g_deg[i];
        g_rowptr[i] = run;
        g_cursor[i] = run;
        run += dg;
    }
    if (t == SCAN_T - 1) g_rowptr[NN] = run;
}

__global__ void k_fill(const int* __restrict__ ei, int Eo, int Et) {
    int e = blockIdx.x * blockDim.x + threadIdx.x;
    if (e >= Et) return;
    int s, d;
    edge_sd(ei, Eo, e, s, d);
    if ((unsigned)s >= NN || (unsigned)d >= NN) return;
    int pos = atomicAdd(&g_cursor[d], 1);
    g_csr[pos] = s;
}

// ---------------- GEMM1: xh = x[N,128] @ W1[128,256] ----------------
__global__ void k_gemm1(const float* __restrict__ x, const float* __restrict__ W1) {
    __shared__ float xs[16 * 128];   // k-major: xs[k][row]
    __shared__ float ws[16 * 64];    // ws[k][col]
    int tid = threadIdx.x;
    int r0 = blockIdx.x * 128;
    int c0 = blockIdx.y * 64;
    int tx = tid & 15;
    int ty = tid >> 4;
    float acc[8][4];
#pragma unroll
    for (int i = 0; i < 8; i++)
#pragma unroll
        for (int j = 0; j < 4; j++) acc[i][j] = 0.f;

    for (int k0 = 0; k0 < 128; k0 += 16) {
#pragma unroll
        for (int i = 0; i < 2; i++) {
            int f = tid + i * 256;
            int row = f >> 2;
            int kq = f & 3;
            int gr = r0 + row;
            float4 v = make_float4(0.f, 0.f, 0.f, 0.f);
            if (gr < NN) v = *(const float4*)(x + (size_t)gr * 128 + k0 + kq * 4);
            xs[(kq * 4 + 0) * 128 + row] = v.x;
            xs[(kq * 4 + 1) * 128 + row] = v.y;
            xs[(kq * 4 + 2) * 128 + row] = v.z;
            xs[(kq * 4 + 3) * 128 + row] = v.w;
        }
        {
            int k = tid >> 4;
            int cq = tid & 15;
            float4 v = *(const float4*)(W1 + (size_t)(k0 + k) * 256 + c0 + cq * 4);
            *(float4*)(ws + k * 64 + cq * 4) = v;
        }
        __syncthreads();
#pragma unroll
        for (int kk = 0; kk < 16; kk++) {
            float4 b  = *(float4*)(ws + kk * 64 + tx * 4);
            float4 a0 = *(float4*)(xs + kk * 128 + ty * 8);
            float4 a1 = *(float4*)(xs + kk * 128 + ty * 8 + 4);
            float av[8] = {a0.x, a0.y, a0.z, a0.w, a1.x, a1.y, a1.z, a1.w};
#pragma unroll
            for (int i = 0; i < 8; i++) {
                acc[i][0] += av[i] * b.x;
                acc[i][1] += av[i] * b.y;
                acc[i][2] += av[i] * b.z;
                acc[i][3] += av[i] * b.w;
            }
        }
        __syncthreads();
    }
#pragma unroll
    for (int i = 0; i < 8; i++) {
        int gr = r0 + ty * 8 + i;
        if (gr < NN)
            *(float4*)(g_xh + (size_t)gr * 256 + c0 + tx * 4) =
                make_float4(acc[i][0], acc[i][1], acc[i][2], acc[i][3]);
    }
}

// ---------------- attention coefficients, layer 1 (warp per node) ----------------
__global__ void k_coef1(const float* __restrict__ as, const float* __restrict__ ad) {
    int w = (blockIdx.x * blockDim.x + threadIdx.x) >> 5;
    int lane = threadIdx.x & 31;
    if (w >= NN) return;
    const float4* xr = (const float4*)(g_xh + (size_t)w * 256);
    float4 v0 = xr[lane * 2], v1 = xr[lane * 2 + 1];
    const float4* a4 = (const float4*)as;
    const float4* d4 = (const float4*)ad;
    float4 s0 = a4[lane * 2], s1v = a4[lane * 2 + 1];
    float4 d0 = d4[lane * 2], d1v = d4[lane * 2 + 1];
    float ps = v0.x * s0.x + v0.y * s0.y + v0.z * s0.z + v0.w * s0.w
             + v1.x * s1v.x + v1.y * s1v.y + v1.z * s1v.z + v1.w * s1v.w;
    float pd = v0.x * d0.x + v0.y * d0.y + v0.z * d0.z + v0.w * d0.w
             + v1.x * d1v.x + v1.y * d1v.y + v1.z * d1v.z + v1.w * d1v.w;
    ps += __shfl_xor_sync(0xffffffffu, ps, 1);
    ps += __shfl_xor_sync(0xffffffffu, ps, 2);
    pd += __shfl_xor_sync(0xffffffffu, pd, 1);
    pd += __shfl_xor_sync(0xffffffffu, pd, 2);
    if ((lane & 3) == 0) {
        g_e1s[w * 8 + (lane >> 2)] = ps;
        g_e1d[w * 8 + (lane >> 2)] = pd;
    }
}

// ---------------- layer-1 CSR aggregate + finalize (warp per node) ----------------
// lane covers channels [lane*8, lane*8+8); head = lane>>2.
// No segment-max: exp(e) is overflow-safe at these magnitudes; alpha invariant.
__global__ void k_agg1c(const float* __restrict__ b1) {
    int node = (blockIdx.x * blockDim.x + threadIdx.x) >> 5;
    int lane = threadIdx.x & 31;
    if (node >= NN) return;
    int beg = g_rowptr[node], end = g_rowptr[node + 1];
    int h = lane >> 2;
    float ed = g_e1d[node * 8 + h];
    float a0 = 0.f, a1 = 0.f, a2 = 0.f, a3 = 0.f;
    float a4 = 0.f, a5 = 0.f, a6 = 0.f, a7 = 0.f;
    float ssum = 0.f;
    for (int i = beg; i < end; i++) {
        int s = g_csr[i];
        float p = __expf(lrelu(g_e1s[s * 8 + h] + ed));
        ssum += p;   // identical across the 4 lanes of a head group
        const float4* xr = (const float4*)(g_xh + (size_t)s * 256 + lane * 8);
        float4 v0 = xr[0], v1 = xr[1];
        a0 += p * v0.x; a1 += p * v0.y; a2 += p * v0.z; a3 += p * v0.w;
        a4 += p * v1.x; a5 += p * v1.y; a6 += p * v1.z; a7 += p * v1.w;
    }
    float inv = 1.f / (ssum + 1e-16f);
    const float4* bb = (const float4*)(b1 + lane * 8);
    float4 b0 = bb[0], b1v = bb[1];
    float4 o0, o1;
    o0.x = fmaxf(a0 * inv + b0.x, 0.f);  o0.y = fmaxf(a1 * inv + b0.y, 0.f);
    o0.z = fmaxf(a2 * inv + b0.z, 0.f);  o0.w = fmaxf(a3 * inv + b0.w, 0.f);
    o1.x = fmaxf(a4 * inv + b1v.x, 0.f); o1.y = fmaxf(a5 * inv + b1v.y, 0.f);
    o1.z = fmaxf(a6 * inv + b1v.z, 0.f); o1.w = fmaxf(a7 * inv + b1v.w, 0.f);
    float4* dst = (float4*)(g_h + (size_t)node * 256 + lane * 8);
    dst[0] = o0;
    dst[1] = o1;
}

// ---------------- GEMM2: h2 = h[N,256] @ W2[256,32] ----------------
__global__ void k_gemm2(const float* __restrict__ W2) {
    __shared__ float hs[32 * 64];
    __shared__ float ws[32 * 32];
    int tid = threadIdx.x;
    int r0 = blockIdx.x * 64;
    int tx = tid & 7;
    int ty = tid >> 3;
    float acc[2][4];
#pragma unroll
    for (int i = 0; i < 2; i++)
#pragma unroll
        for (int j = 0; j < 4; j++) acc[i][j] = 0.f;

    for (int k0 = 0; k0 < 256; k0 += 32) {
#pragma unroll
        for (int i = 0; i < 2; i++) {
            int f = tid + i * 256;
            int row = f >> 3;
            int kq = f & 7;
            int gr = r0 + row;
            float4 v = make_float4(0.f, 0.f, 0.f, 0.f);
            if (gr < NN) v = *(const float4*)(g_h + (size_t)gr * 256 + k0 + kq * 4);
            hs[(kq * 4 + 0) * 64 + row] = v.x;
            hs[(kq * 4 + 1) * 64 + row] = v.y;
            hs[(kq * 4 + 2) * 64 + row] = v.z;
            hs[(kq * 4 + 3) * 64 + row] = v.w;
        }
        {
            int k = tid >> 3;
            int cq = tid & 7;
            *(float4*)(ws + k * 32 + cq * 4) =
                *(const float4*)(W2 + (size_t)(k0 + k) * 32 + cq * 4);
        }
        __syncthreads();
#pragma unroll
        for (int kk = 0; kk < 32; kk++) {
            float2 a = *(float2*)(hs + kk * 64 + ty * 2);
            float4 b = *(float4*)(ws + kk * 32 + tx * 4);
            acc[0][0] += a.x * b.x; acc[0][1] += a.x * b.y;
            acc[0][2] += a.x * b.z; acc[0][3] += a.x * b.w;
            acc[1][0] += a.y * b.x; acc[1][1] += a.y * b.y;
            acc[1][2] += a.y * b.z; acc[1][3] += a.y * b.w;
        }
        __syncthreads();
    }
#pragma unroll
    for (int i = 0; i < 2; i++) {
        int gr = r0 + ty * 2 + i;
        if (gr < NN)
            *(float4*)(g_h2 + (size_t)gr * 32 + tx * 4) =
                make_float4(acc[i][0], acc[i][1], acc[i][2], acc[i][3]);
    }
}

// ---------------- coefficients, layer 2 (thread per node) ----------------
__global__ void k_coef2(const float* __restrict__ as, const float* __restrict__ ad) {
    int n = blockIdx.x * blockDim.x + threadIdx.x;
    if (n >= NN) return;
    const float4* h4 = (const float4*)(g_h2 + (size_t)n * 32);
    float ps = 0.f, pd = 0.f;
#pragma unroll
    for (int j = 0; j < 8; j++) {
        float4 v = h4[j];
        float4 a = ((const float4*)as)[j];
        float4 b = ((const float4*)ad)[j];
        ps += v.x * a.x + v.y * a.y + v.z * a.z + v.w * a.w;
        pd += v.x * b.x + v.y * b.y + v.z * b.z + v.w * b.w;
    }
    g_e2s[n] = ps;
    g_e2d[n] = pd;
}

// ---------------- layer-2 CSR aggregate + finalize (warp per node) ----------------
__global__ void k_agg2c(float* __restrict__ out, const float* __restrict__ b2) {
    int node = (blockIdx.x * blockDim.x + threadIdx.x) >> 5;
    int lane = threadIdx.x & 31;
    if (node >= NN) return;
    int beg = g_rowptr[node], end = g_rowptr[node + 1];
    float ed = g_e2d[node];
    float acc = 0.f, ssum = 0.f;
    for (int i = beg; i < end; i++) {
        int s = g_csr[i];
        float p = __expf(lrelu(g_e2s[s] + ed));
        ssum += p;
        acc += p * g_h2[(size_t)s * 32 + lane];
    }
    out[(size_t)node * 32 + lane] = acc / (ssum + 1e-16f) + b2[lane];
}

// ---------------- launch ----------------
extern "C" void kernel_launch(void* const* d_in, const int* in_sizes, int n_in,
                              void* d_out, int out_size) {
    const float* x   = (const float*)d_in[0];
    const int*   ei  = (const int*)d_in[1];
    const float* W1  = (const float*)d_in[2];
    const float* as1 = (const float*)d_in[3];
    const float* ad1 = (const float*)d_in[4];
    const float* b1  = (const float*)d_in[5];
    const float* W2  = (const float*)d_in[6];
    const float* as2 = (const float*)d_in[7];
    const float* ad2 = (const float*)d_in[8];
    const float* b2  = (const float*)d_in[9];

    int Eo = in_sizes[1] / 2;
    if (Eo > EE) Eo = EE;
    int Et = Eo + NN;

    k_detect<<<1, 32>>>(ei);
    k_zero<<<(NN + 255) / 256, 256>>>();
    k_hist<<<(Et + 255) / 256, 256>>>(ei, Eo, Et);
    k_scan<<<1, SCAN_T>>>();
    k_fill<<<(Et + 255) / 256, 256>>>(ei, Eo, Et);

    dim3 g1((NN + 127) / 128, C1 / 64);
    k_gemm1<<<g1, 256>>>(x, W1);
    k_coef1<<<(NN * 32 + 255) / 256, 256>>>(as1, ad1);
    k_agg1c<<<(NN * 32 + 255) / 256, 256>>>(b1);

    k_gemm2<<<(NN + 63) / 64, 256>>>(W2);
    k_coef2<<<(NN + 255) / 256, 256>>>(as2, ad2);
    k_agg2c<<<(NN * 32 + 255) / 256, 256>>>((float*)d_out, b2);
}

// round 6
// speedup vs baseline: 2.4354x; 1.2838x over previous
#include <cuda_runtime.h>
#include <cstdint>

#define NN 100000
#define EE 1600000
#define ETOT (EE + NN)
#define C1 256          // HEADS*HID
#define HEADS 8
#define HID 32
#define NEG 0.2f
#define SCB 1024                      // scan chunk per block
#define NBLK ((NN + SCB - 1) / SCB)   // 98

// ---------------- scratch (static device allocations) ----------------
static __device__ float g_xh [(size_t)NN * C1];   // layer1 projected features
static __device__ float g_e1s[NN * HEADS];
static __device__ float g_e1d[NN * HEADS];
static __device__ float g_h  [(size_t)NN * C1];   // relu(layer1 out)
static __device__ float g_h2 [NN * HID];          // layer2 projected
static __device__ float g_e2s[NN];
static __device__ float g_e2d[NN];
static __device__ int   g_deg[NN];
static __device__ int   g_rowptr[NN + 1];
static __device__ int   g_cursor[NN];
static __device__ int   g_csr[ETOT];              // src ids grouped by dst
static __device__ int   g_bsum[NBLK];
static __device__ int   g_boff[NBLK];
static __device__ int   g_is64;                   // edge_index dtype flag

// ---------------- helpers ----------------
__device__ __forceinline__ float lrelu(float x) { return x > 0.f ? x : NEG * x; }

__device__ __forceinline__ void edge_sd(const int* __restrict__ ei, int Eo,
                                        int e, int& s, int& d) {
    if (e < Eo) {
        if (g_is64) { s = ei[2 * e]; d = ei[2 * (Eo + e)]; }
        else        { s = ei[e];     d = ei[Eo + e]; }
    } else {
        s = e - Eo; d = s;   // self-loop
    }
}

// ---------------- dtype probe ----------------
__global__ void k_detect(const int* __restrict__ ei) {
    if (threadIdx.x == 0 && blockIdx.x == 0) {
        int all0 = 1;
        for (int i = 0; i < 128; i++)
            if (ei[2 * i + 1] != 0) { all0 = 0; break; }
        g_is64 = all0;
    }
}

// ---------------- CSR build ----------------
__global__ void k_zero() {
    int i = blockIdx.x * blockDim.x + threadIdx.x;
    if (i < NN) g_deg[i] = 0;
}

__global__ void k_hist(const int* __restrict__ ei, int Eo, int Et) {
    int e = blockIdx.x * blockDim.x + threadIdx.x;
    if (e >= Et) return;
    int s, d;
    edge_sd(ei, Eo, e, s, d);
    if ((unsigned)d >= NN) return;
    atomicAdd(&g_deg[d], 1);
}

// scan phase A: per-block (1024-elem chunk) reduction
__global__ void k_scan_a() {
    __shared__ int sh[32];
    int i = blockIdx.x * SCB + threadIdx.x;
    int v = (i < NN) ? g_deg[i] : 0;
#pragma unroll
    for (int o = 16; o > 0; o >>= 1) v += __shfl_down_sync(0xffffffffu, v, o);
    if ((threadIdx.x & 31) == 0) sh[threadIdx.x >> 5] = v;
    __syncthreads();
    if (threadIdx.x < 32) {
        int w = (threadIdx.x < (SCB / 32)) ? sh[threadIdx.x] : 0;
#pragma unroll
        for (int o = 16; o > 0; o >>= 1) w += __shfl_down_sync(0xffffffffu, w, o);
        if (threadIdx.x == 0) g_bsum[blockIdx.x] = w;
    }
}

// scan phase B: exclusive scan of the NBLK block sums (1 small block)
__global__ void k_scan_b() {
    __shared__ int sh[NBLK];
    int t = threadIdx.x;
    if (t < NBLK) sh[t] = g_bsum[t];
    __syncthreads();
    if (t == 0) {
        int run = 0;
        for (int b = 0; b < NBLK; b++) { int v = sh[b]; sh[b] = run; run += v; }
        g_rowptr[NN] = run;
    }
    __syncthreads();
    if (t < NBLK) g_boff[t] = sh[t];
}

// scan phase C: in-block inclusive scan + block offset -> rowptr/cursor
__global__ void k_scan_c() {
    __shared__ int sh[SCB];
    int t = threadIdx.x;
    int i = blockIdx.x * SCB + t;
    sh[t] = (i < NN) ? g_deg[i] : 0;
    __syncthreads();
#pragma unroll
    for (int off = 1; off < SCB; off <<= 1) {
        int v = (t >= off) ? sh[t - off] : 0;
        __syncthreads();
        sh[t] += v;
        __syncthreads();
    }
    if (i < NN) {
        int excl = g_boff[blockIdx.x] + sh[t] - g_deg[i];  // exclusive prefix
        g_rowptr[i] = excl;
        g_cursor[i] = excl;
    }
}

__global__ void k_fill(const int* __restrict__ ei, int Eo, int Et) {
    int e = blockIdx.x * blockDim.x + threadIdx.x;
    if (e >= Et) return;
    int s, d;
    edge_sd(ei, Eo, e, s, d);
    if ((unsigned)s >= NN || (unsigned)d >= NN) return;
    int pos = atomicAdd(&g_cursor[d], 1);
    g_csr[pos] = s;
}

// ---------------- GEMM1: xh = x[N,128] @ W1[128,256] ----------------
__global__ void k_gemm1(const float* __restrict__ x, const float* __restrict__ W1) {
    __shared__ float xs[16 * 128];   // k-major: xs[k][row]
    __shared__ float ws[16 * 64];    // ws[k][col]
    int tid = threadIdx.x;
    int r0 = blockIdx.x * 128;
    int c0 = blockIdx.y * 64;
    int tx = tid & 15;
    int ty = tid >> 4;
    float acc[8][4];
#pragma unroll
    for (int i = 0; i < 8; i++)
#pragma unroll
        for (int j = 0; j < 4; j++) acc[i][j] = 0.f;

    for (int k0 = 0; k0 < 128; k0 += 16) {
#pragma unroll
        for (int i = 0; i < 2; i++) {
            int f = tid + i * 256;
            int row = f >> 2;
            int kq = f & 3;
            int gr = r0 + row;
            float4 v = make_float4(0.f, 0.f, 0.f, 0.f);
            if (gr < NN) v = *(const float4*)(x + (size_t)gr * 128 + k0 + kq * 4);
            xs[(kq * 4 + 0) * 128 + row] = v.x;
            xs[(kq * 4 + 1) * 128 + row] = v.y;
            xs[(kq * 4 + 2) * 128 + row] = v.z;
            xs[(kq * 4 + 3) * 128 + row] = v.w;
        }
        {
            int k = tid >> 4;
            int cq = tid & 15;
            float4 v = *(const float4*)(W1 + (size_t)(k0 + k) * 256 + c0 + cq * 4);
            *(float4*)(ws + k * 64 + cq * 4) = v;
        }
        __syncthreads();
#pragma unroll
        for (int kk = 0; kk < 16; kk++) {
            float4 b  = *(float4*)(ws + kk * 64 + tx * 4);
            float4 a0 = *(float4*)(xs + kk * 128 + ty * 8);
            float4 a1 = *(float4*)(xs + kk * 128 + ty * 8 + 4);
            float av[8] = {a0.x, a0.y, a0.z, a0.w, a1.x, a1.y, a1.z, a1.w};
#pragma unroll
            for (int i = 0; i < 8; i++) {
                acc[i][0] += av[i] * b.x;
                acc[i][1] += av[i] * b.y;
                acc[i][2] += av[i] * b.z;
                acc[i][3] += av[i] * b.w;
            }
        }
        __syncthreads();
    }
#pragma unroll
    for (int i = 0; i < 8; i++) {
        int gr = r0 + ty * 8 + i;
        if (gr < NN)
            *(float4*)(g_xh + (size_t)gr * 256 + c0 + tx * 4) =
                make_float4(acc[i][0], acc[i][1], acc[i][2], acc[i][3]);
    }
}

// ---------------- attention coefficients, layer 1 (warp per node) ----------------
__global__ void k_coef1(const float* __restrict__ as, const float* __restrict__ ad) {
    int w = (blockIdx.x * blockDim.x + threadIdx.x) >> 5;
    int lane = threadIdx.x & 31;
    if (w >= NN) return;
    const float4* xr = (const float4*)(g_xh + (size_t)w * 256);
    float4 v0 = xr[lane * 2], v1 = xr[lane * 2 + 1];
    const float4* a4 = (const float4*)as;
    const float4* d4 = (const float4*)ad;
    float4 s0 = a4[lane * 2], s1v = a4[lane * 2 + 1];
    float4 d0 = d4[lane * 2], d1v = d4[lane * 2 + 1];
    float ps = v0.x * s0.x + v0.y * s0.y + v0.z * s0.z + v0.w * s0.w
             + v1.x * s1v.x + v1.y * s1v.y + v1.z * s1v.z + v1.w * s1v.w;
    float pd = v0.x * d0.x + v0.y * d0.y + v0.z * d0.z + v0.w * d0.w
             + v1.x * d1v.x + v1.y * d1v.y + v1.z * d1v.z + v1.w * d1v.w;
    ps += __shfl_xor_sync(0xffffffffu, ps, 1);
    ps += __shfl_xor_sync(0xffffffffu, ps, 2);
    pd += __shfl_xor_sync(0xffffffffu, pd, 1);
    pd += __shfl_xor_sync(0xffffffffu, pd, 2);
    if ((lane & 3) == 0) {
        g_e1s[w * 8 + (lane >> 2)] = ps;
        g_e1d[w * 8 + (lane >> 2)] = pd;
    }
}

// ---------------- layer-1 CSR aggregate + finalize (warp per node) ----------------
__global__ void k_agg1c(const float* __restrict__ b1) {
    int node = (blockIdx.x * blockDim.x + threadIdx.x) >> 5;
    int lane = threadIdx.x & 31;
    if (node >= NN) return;
    int beg = g_rowptr[node], end = g_rowptr[node + 1];
    int h = lane >> 2;
    float ed = g_e1d[node * 8 + h];
    float a0 = 0.f, a1 = 0.f, a2 = 0.f, a3 = 0.f;
    float a4 = 0.f, a5 = 0.f, a6 = 0.f, a7 = 0.f;
    float ssum = 0.f;
    for (int i = beg; i < end; i++) {
        int s = g_csr[i];
        float p = __expf(lrelu(g_e1s[s * 8 + h] + ed));
        ssum += p;
        const float4* xr = (const float4*)(g_xh + (size_t)s * 256 + lane * 8);
        float4 v0 = xr[0], v1 = xr[1];
        a0 += p * v0.x; a1 += p * v0.y; a2 += p * v0.z; a3 += p * v0.w;
        a4 += p * v1.x; a5 += p * v1.y; a6 += p * v1.z; a7 += p * v1.w;
    }
    float inv = 1.f / (ssum + 1e-16f);
    const float4* bb = (const float4*)(b1 + lane * 8);
    float4 b0 = bb[0], b1v = bb[1];
    float4 o0, o1;
    o0.x = fmaxf(a0 * inv + b0.x, 0.f);  o0.y = fmaxf(a1 * inv + b0.y, 0.f);
    o0.z = fmaxf(a2 * inv + b0.z, 0.f);  o0.w = fmaxf(a3 * inv + b0.w, 0.f);
    o1.x = fmaxf(a4 * inv + b1v.x, 0.f); o1.y = fmaxf(a5 * inv + b1v.y, 0.f);
    o1.z = fmaxf(a6 * inv + b1v.z, 0.f); o1.w = fmaxf(a7 * inv + b1v.w, 0.f);
    float4* dst = (float4*)(g_h + (size_t)node * 256 + lane * 8);
    dst[0] = o0;
    dst[1] = o1;
}

// ---------------- GEMM2: h2 = h[N,256] @ W2[256,32] ----------------
__global__ void k_gemm2(const float* __restrict__ W2) {
    __shared__ float hs[32 * 64];
    __shared__ float ws[32 * 32];
    int tid = threadIdx.x;
    int r0 = blockIdx.x * 64;
    int tx = tid & 7;
    int ty = tid >> 3;
    float acc[2][4];
#pragma unroll
    for (int i = 0; i < 2; i++)
#pragma unroll
        for (int j = 0; j < 4; j++) acc[i][j] = 0.f;

    for (int k0 = 0; k0 < 256; k0 += 32) {
#pragma unroll
        for (int i = 0; i < 2; i++) {
            int f = tid + i * 256;
            int row = f >> 3;
            int kq = f & 7;
            int gr = r0 + row;
            float4 v = make_float4(0.f, 0.f, 0.f, 0.f);
            if (gr < NN) v = *(const float4*)(g_h + (size_t)gr * 256 + k0 + kq * 4);
            hs[(kq * 4 + 0) * 64 + row] = v.x;
            hs[(kq * 4 + 1) * 64 + row] = v.y;
            hs[(kq * 4 + 2) * 64 + row] = v.z;
            hs[(kq * 4 + 3) * 64 + row] = v.w;
        }
        {
            int k = tid >> 3;
            int cq = tid & 7;
            *(float4*)(ws + k * 32 + cq * 4) =
                *(const float4*)(W2 + (size_t)(k0 + k) * 32 + cq * 4);
        }
        __syncthreads();
#pragma unroll
        for (int kk = 0; kk < 32; kk++) {
            float2 a = *(float2*)(hs + kk * 64 + ty * 2);
            float4 b = *(float4*)(ws + kk * 32 + tx * 4);
            acc[0][0] += a.x * b.x; acc[0][1] += a.x * b.y;
            acc[0][2] += a.x * b.z; acc[0][3] += a.x * b.w;
            acc[1][0] += a.y * b.x; acc[1][1] += a.y * b.y;
            acc[1][2] += a.y * b.z; acc[1][3] += a.y * b.w;
        }
        __syncthreads();
    }
#pragma unroll
    for (int i = 0; i < 2; i++) {
        int gr = r0 + ty * 2 + i;
        if (gr < NN)
            *(float4*)(g_h2 + (size_t)gr * 32 + tx * 4) =
                make_float4(acc[i][0], acc[i][1], acc[i][2], acc[i][3]);
    }
}

// ---------------- coefficients, layer 2 (thread per node) ----------------
__global__ void k_coef2(const float* __restrict__ as, const float* __restrict__ ad) {
    int n = blockIdx.x * blockDim.x + threadIdx.x;
    if (n >= NN) return;
    const float4* h4 = (const float4*)(g_h2 + (size_t)n * 32);
    float ps = 0.f, pd = 0.f;
#pragma unroll
    for (int j = 0; j < 8; j++) {
        float4 v = h4[j];
        float4 a = ((const float4*)as)[j];
        float4 b = ((const float4*)ad)[j];
        ps += v.x * a.x + v.y * a.y + v.z * a.z + v.w * a.w;
        pd += v.x * b.x + v.y * b.y + v.z * b.z + v.w * b.w;
    }
    g_e2s[n] = ps;
    g_e2d[n] = pd;
}

// ---------------- layer-2 CSR aggregate + finalize (warp per node) ----------------
__global__ void k_agg2c(float* __restrict__ out, const float* __restrict__ b2) {
    int node = (blockIdx.x * blockDim.x + threadIdx.x) >> 5;
    int lane = threadIdx.x & 31;
    if (node >= NN) return;
    int beg = g_rowptr[node], end = g_rowptr[node + 1];
    float ed = g_e2d[node];
    float acc = 0.f, ssum = 0.f;
    for (int i = beg; i < end; i++) {
        int s = g_csr[i];
        float p = __expf(lrelu(g_e2s[s] + ed));
        ssum += p;
        acc += p * g_h2[(size_t)s * 32 + lane];
    }
    out[(size_t)node * 32 + lane] = acc / (ssum + 1e-16f) + b2[lane];
}

// ---------------- launch ----------------
extern "C" void kernel_launch(void* const* d_in, const int* in_sizes, int n_in,
                              void* d_out, int out_size) {
    const float* x   = (const float*)d_in[0];
    const int*   ei  = (const int*)d_in[1];
    const float* W1  = (const float*)d_in[2];
    const float* as1 = (const float*)d_in[3];
    const float* ad1 = (const float*)d_in[4];
    const float* b1  = (const float*)d_in[5];
    const float* W2  = (const float*)d_in[6];
    const float* as2 = (const float*)d_in[7];
    const float* ad2 = (const float*)d_in[8];
    const float* b2  = (const float*)d_in[9];

    int Eo = in_sizes[1] / 2;
    if (Eo > EE) Eo = EE;
    int Et = Eo + NN;

    k_detect<<<1, 32>>>(ei);
    k_zero<<<(NN + 255) / 256, 256>>>();
    k_hist<<<(Et + 255) / 256, 256>>>(ei, Eo, Et);
    k_scan_a<<<NBLK, SCB>>>();
    k_scan_b<<<1, 128>>>();
    k_scan_c<<<NBLK, SCB>>>();
    k_fill<<<(Et + 255) / 256, 256>>>(ei, Eo, Et);

    dim3 g1((NN + 127) / 128, C1 / 64);
    k_gemm1<<<g1, 256>>>(x, W1);
    k_coef1<<<(NN * 32 + 255) / 256, 256>>>(as1, ad1);
    k_agg1c<<<(NN * 32 + 255) / 256, 256>>>(b1);

    k_gemm2<<<(NN + 63) / 64, 256>>>(W2);
    k_coef2<<<(NN + 255) / 256, 256>>>(as2, ad2);
    k_agg2c<<<(NN * 32 + 255) / 256, 256>>>((float*)d_out, b2);
}

// round 7
// speedup vs baseline: 2.8446x; 1.1680x over previous
#include <cuda_runtime.h>
#include <cuda_fp16.h>
#include <cstdint>

#define NN 100000
#define EE 1600000
#define ETOT (EE + NN)
#define C1 256          // HEADS*HID
#define HEADS 8
#define HID 32
#define NEG 0.2f
#define SCB 1024                      // scan chunk per block
#define NBLK ((NN + SCB - 1) / SCB)   // 98

// ---------------- scratch (static device allocations) ----------------
static __device__ __half2 g_xh [(size_t)NN * (C1 / 2)];  // layer1 projected (fp16)
static __device__ float g_e1s[NN * HEADS];
static __device__ float g_e1d[NN * HEADS];
static __device__ float g_h  [(size_t)NN * C1];   // relu(layer1 out)
static __device__ float g_h2 [NN * HID];          // layer2 projected
static __device__ float g_e2s[NN];
static __device__ float g_e2d[NN];
static __device__ int   g_deg[NN];
static __device__ int   g_rowptr[NN + 1];
static __device__ int   g_cursor[NN];
static __device__ int   g_csr[ETOT];              // src ids grouped by dst
static __device__ int   g_bsum[NBLK];
static __device__ int   g_boff[NBLK];
static __device__ int   g_is64;                   // edge_index dtype flag

// ---------------- helpers ----------------
__device__ __forceinline__ float lrelu(float x) { return x > 0.f ? x : NEG * x; }

__device__ __forceinline__ void edge_sd(const int* __restrict__ ei, int Eo,
                                        int e, int& s, int& d) {
    if (e < Eo) {
        if (g_is64) { s = ei[2 * e]; d = ei[2 * (Eo + e)]; }
        else        { s = ei[e];     d = ei[Eo + e]; }
    } else {
        s = e - Eo; d = s;   // self-loop
    }
}

// ---------------- dtype probe ----------------
__global__ void k_detect(const int* __restrict__ ei) {
    if (threadIdx.x == 0 && blockIdx.x == 0) {
        int all0 = 1;
        for (int i = 0; i < 128; i++)
            if (ei[2 * i + 1] != 0) { all0 = 0; break; }
        g_is64 = all0;
    }
}

// ---------------- CSR build ----------------
__global__ void k_zero() {
    int i = blockIdx.x * blockDim.x + threadIdx.x;
    if (i < NN) g_deg[i] = 0;
}

__global__ void k_hist(const int* __restrict__ ei, int Eo, int Et) {
    int e = blockIdx.x * blockDim.x + threadIdx.x;
    if (e >= Et) return;
    int s, d;
    edge_sd(ei, Eo, e, s, d);
    if ((unsigned)d >= NN) return;
    atomicAdd(&g_deg[d], 1);
}

__global__ void k_scan_a() {
    __shared__ int sh[32];
    int i = blockIdx.x * SCB + threadIdx.x;
    int v = (i < NN) ? g_deg[i] : 0;
#pragma unroll
    for (int o = 16; o > 0; o >>= 1) v += __shfl_down_sync(0xffffffffu, v, o);
    if ((threadIdx.x & 31) == 0) sh[threadIdx.x >> 5] = v;
    __syncthreads();
    if (threadIdx.x < 32) {
        int w = (threadIdx.x < (SCB / 32)) ? sh[threadIdx.x] : 0;
#pragma unroll
        for (int o = 16; o > 0; o >>= 1) w += __shfl_down_sync(0xffffffffu, w, o);
        if (threadIdx.x == 0) g_bsum[blockIdx.x] = w;
    }
}

__global__ void k_scan_b() {
    __shared__ int sh[NBLK];
    int t = threadIdx.x;
    if (t < NBLK) sh[t] = g_bsum[t];
    __syncthreads();
    if (t == 0) {
        int run = 0;
        for (int b = 0; b < NBLK; b++) { int v = sh[b]; sh[b] = run; run += v; }
        g_rowptr[NN] = run;
    }
    __syncthreads();
    if (t < NBLK) g_boff[t] = sh[t];
}

__global__ void k_scan_c() {
    __shared__ int sh[SCB];
    int t = threadIdx.x;
    int i = blockIdx.x * SCB + t;
    sh[t] = (i < NN) ? g_deg[i] : 0;
    __syncthreads();
#pragma unroll
    for (int off = 1; off < SCB; off <<= 1) {
        int v = (t >= off) ? sh[t - off] : 0;
        __syncthreads();
        sh[t] += v;
        __syncthreads();
    }
    if (i < NN) {
        int excl = g_boff[blockIdx.x] + sh[t] - g_deg[i];
        g_rowptr[i] = excl;
        g_cursor[i] = excl;
    }
}

__global__ void k_fill(const int* __restrict__ ei, int Eo, int Et) {
    int e = blockIdx.x * blockDim.x + threadIdx.x;
    if (e >= Et) return;
    int s, d;
    edge_sd(ei, Eo, e, s, d);
    if ((unsigned)s >= NN || (unsigned)d >= NN) return;
    int pos = atomicAdd(&g_cursor[d], 1);
    g_csr[pos] = s;
}

// ---------------- GEMM1: xh = x[N,128] @ W1[128,256] -> fp16 ----------------
__global__ void k_gemm1(const float* __restrict__ x, const float* __restrict__ W1) {
    __shared__ float xs[16 * 128];   // k-major: xs[k][row]
    __shared__ float ws[16 * 64];    // ws[k][col]
    int tid = threadIdx.x;
    int r0 = blockIdx.x * 128;
    int c0 = blockIdx.y * 64;
    int tx = tid & 15;
    int ty = tid >> 4;
    float acc[8][4];
#pragma unroll
    for (int i = 0; i < 8; i++)
#pragma unroll
        for (int j = 0; j < 4; j++) acc[i][j] = 0.f;

    for (int k0 = 0; k0 < 128; k0 += 16) {
#pragma unroll
        for (int i = 0; i < 2; i++) {
            int f = tid + i * 256;
            int row = f >> 2;
            int kq = f & 3;
            int gr = r0 + row;
            float4 v = make_float4(0.f, 0.f, 0.f, 0.f);
            if (gr < NN) v = *(const float4*)(x + (size_t)gr * 128 + k0 + kq * 4);
            xs[(kq * 4 + 0) * 128 + row] = v.x;
            xs[(kq * 4 + 1) * 128 + row] = v.y;
            xs[(kq * 4 + 2) * 128 + row] = v.z;
            xs[(kq * 4 + 3) * 128 + row] = v.w;
        }
        {
            int k = tid >> 4;
            int cq = tid & 15;
            float4 v = *(const float4*)(W1 + (size_t)(k0 + k) * 256 + c0 + cq * 4);
            *(float4*)(ws + k * 64 + cq * 4) = v;
        }
        __syncthreads();
#pragma unroll
        for (int kk = 0; kk < 16; kk++) {
            float4 b  = *(float4*)(ws + kk * 64 + tx * 4);
            float4 a0 = *(float4*)(xs + kk * 128 + ty * 8);
            float4 a1 = *(float4*)(xs + kk * 128 + ty * 8 + 4);
            float av[8] = {a0.x, a0.y, a0.z, a0.w, a1.x, a1.y, a1.z, a1.w};
#pragma unroll
            for (int i = 0; i < 8; i++) {
                acc[i][0] += av[i] * b.x;
                acc[i][1] += av[i] * b.y;
                acc[i][2] += av[i] * b.z;
                acc[i][3] += av[i] * b.w;
            }
        }
        __syncthreads();
    }
#pragma unroll
    for (int i = 0; i < 8; i++) {
        int gr = r0 + ty * 8 + i;
        if (gr < NN) {
            __half2 h0 = __floats2half2_rn(acc[i][0], acc[i][1]);
            __half2 h1 = __floats2half2_rn(acc[i][2], acc[i][3]);
            __half2* dst = g_xh + (size_t)gr * (C1 / 2) + (c0 >> 1) + tx * 2;
            dst[0] = h0;
            dst[1] = h1;
        }
    }
}

// ---------------- attention coefficients, layer 1 (warp per node) ----------------
// lane covers channels [lane*8, lane*8+8)
__global__ void k_coef1(const float* __restrict__ as, const float* __restrict__ ad) {
    int w = (blockIdx.x * blockDim.x + threadIdx.x) >> 5;
    int lane = threadIdx.x & 31;
    if (w >= NN) return;
    float4 raw = ((const float4*)(g_xh + (size_t)w * (C1 / 2)))[lane];
    const __half2* hp = (const __half2*)&raw;
    float2 q0 = __half22float2(hp[0]), q1 = __half22float2(hp[1]);
    float2 q2 = __half22float2(hp[2]), q3 = __half22float2(hp[3]);
    const float4* a4 = (const float4*)as;
    const float4* d4 = (const float4*)ad;
    float4 s0 = a4[lane * 2], s1v = a4[lane * 2 + 1];
    float4 d0 = d4[lane * 2], d1v = d4[lane * 2 + 1];
    float ps = q0.x * s0.x + q0.y * s0.y + q1.x * s0.z + q1.y * s0.w
             + q2.x * s1v.x + q2.y * s1v.y + q3.x * s1v.z + q3.y * s1v.w;
    float pd = q0.x * d0.x + q0.y * d0.y + q1.x * d0.z + q1.y * d0.w
             + q2.x * d1v.x + q2.y * d1v.y + q3.x * d1v.z + q3.y * d1v.w;
    ps += __shfl_xor_sync(0xffffffffu, ps, 1);
    ps += __shfl_xor_sync(0xffffffffu, ps, 2);
    pd += __shfl_xor_sync(0xffffffffu, pd, 1);
    pd += __shfl_xor_sync(0xffffffffu, pd, 2);
    if ((lane & 3) == 0) {
        g_e1s[w * 8 + (lane >> 2)] = ps;
        g_e1d[w * 8 + (lane >> 2)] = pd;
    }
}

// ---------------- layer-1 CSR aggregate + finalize (warp per node) ----------------
__global__ void k_agg1c(const float* __restrict__ b1) {
    int node = (blockIdx.x * blockDim.x + threadIdx.x) >> 5;
    int lane = threadIdx.x & 31;
    if (node >= NN) return;
    int beg = g_rowptr[node], end = g_rowptr[node + 1];
    int h = lane >> 2;
    float ed = g_e1d[node * 8 + h];
    float a0 = 0.f, a1 = 0.f, a2 = 0.f, a3 = 0.f;
    float a4 = 0.f, a5 = 0.f, a6 = 0.f, a7 = 0.f;
    float ssum = 0.f;
    for (int i = beg; i < end; i++) {
        int s = g_csr[i];
        float p = __expf(lrelu(g_e1s[s * 8 + h] + ed));
        ssum += p;
        float4 raw = ((const float4*)(g_xh + (size_t)s * (C1 / 2)))[lane];
        const __half2* hp = (const __half2*)&raw;
        float2 q0 = __half22float2(hp[0]), q1 = __half22float2(hp[1]);
        float2 q2 = __half22float2(hp[2]), q3 = __half22float2(hp[3]);
        a0 += p * q0.x; a1 += p * q0.y; a2 += p * q1.x; a3 += p * q1.y;
        a4 += p * q2.x; a5 += p * q2.y; a6 += p * q3.x; a7 += p * q3.y;
    }
    float inv = 1.f / (ssum + 1e-16f);
    const float4* bb = (const float4*)(b1 + lane * 8);
    float4 b0 = bb[0], b1v = bb[1];
    float4 o0, o1;
    o0.x = fmaxf(a0 * inv + b0.x, 0.f);  o0.y = fmaxf(a1 * inv + b0.y, 0.f);
    o0.z = fmaxf(a2 * inv + b0.z, 0.f);  o0.w = fmaxf(a3 * inv + b0.w, 0.f);
    o1.x = fmaxf(a4 * inv + b1v.x, 0.f); o1.y = fmaxf(a5 * inv + b1v.y, 0.f);
    o1.z = fmaxf(a6 * inv + b1v.z, 0.f); o1.w = fmaxf(a7 * inv + b1v.w, 0.f);
    float4* dst = (float4*)(g_h + (size_t)node * 256 + lane * 8);
    dst[0] = o0;
    dst[1] = o1;
}

// ---------------- GEMM2: h2 = h[N,256] @ W2[256,32] ----------------
__global__ void k_gemm2(const float* __restrict__ W2) {
    __shared__ float hs[32 * 64];
    __shared__ float ws[32 * 32];
    int tid = threadIdx.x;
    int r0 = blockIdx.x * 64;
    int tx = tid & 7;
    int ty = tid >> 3;
    float acc[2][4];
#pragma unroll
    for (int i = 0; i < 2; i++)
#pragma unroll
        for (int j = 0; j < 4; j++) acc[i][j] = 0.f;

    for (int k0 = 0; k0 < 256; k0 += 32) {
#pragma unroll
        for (int i = 0; i < 2; i++) {
            int f = tid + i * 256;
            int row = f >> 3;
            int kq = f & 7;
            int gr = r0 + row;
            float4 v = make_float4(0.f, 0.f, 0.f, 0.f);
            if (gr < NN) v = *(const float4*)(g_h + (size_t)gr * 256 + k0 + kq * 4);
            hs[(kq * 4 + 0) * 64 + row] = v.x;
            hs[(kq * 4 + 1) * 64 + row] = v.y;
            hs[(kq * 4 + 2) * 64 + row] = v.z;
            hs[(kq * 4 + 3) * 64 + row] = v.w;
        }
        {
            int k = tid >> 3;
            int cq = tid & 7;
            *(float4*)(ws + k * 32 + cq * 4) =
                *(const float4*)(W2 + (size_t)(k0 + k) * 32 + cq * 4);
        }
        __syncthreads();
#pragma unroll
        for (int kk = 0; kk < 32; kk++) {
            float2 a = *(float2*)(hs + kk * 64 + ty * 2);
            float4 b = *(float4*)(ws + kk * 32 + tx * 4);
            acc[0][0] += a.x * b.x; acc[0][1] += a.x * b.y;
            acc[0][2] += a.x * b.z; acc[0][3] += a.x * b.w;
            acc[1][0] += a.y * b.x; acc[1][1] += a.y * b.y;
            acc[1][2] += a.y * b.z; acc[1][3] += a.y * b.w;
        }
        __syncthreads();
    }
#pragma unroll
    for (int i = 0; i < 2; i++) {
        int gr = r0 + ty * 2 + i;
        if (gr < NN)
            *(float4*)(g_h2 + (size_t)gr * 32 + tx * 4) =
                make_float4(acc[i][0], acc[i][1], acc[i][2], acc[i][3]);
    }
}

// ---------------- coefficients, layer 2 (thread per node) ----------------
__global__ void k_coef2(const float* __restrict__ as, const float* __restrict__ ad) {
    int n = blockIdx.x * blockDim.x + threadIdx.x;
    if (n >= NN) return;
    const float4* h4 = (const float4*)(g_h2 + (size_t)n * 32);
    float ps = 0.f, pd = 0.f;
#pragma unroll
    for (int j = 0; j < 8; j++) {
        float4 v = h4[j];
        float4 a = ((const float4*)as)[j];
        float4 b = ((const float4*)ad)[j];
        ps += v.x * a.x + v.y * a.y + v.z * a.z + v.w * a.w;
        pd += v.x * b.x + v.y * b.y + v.z * b.z + v.w * b.w;
    }
    g_e2s[n] = ps;
    g_e2d[n] = pd;
}

// ---------------- layer-2 CSR aggregate + finalize (warp per node) ----------------
__global__ void k_agg2c(float* __restrict__ out, const float* __restrict__ b2) {
    int node = (blockIdx.x * blockDim.x + threadIdx.x) >> 5;
    int lane = threadIdx.x & 31;
    if (node >= NN) return;
    int beg = g_rowptr[node], end = g_rowptr[node + 1];
    float ed = g_e2d[node];
    float acc = 0.f, ssum = 0.f;
    for (int i = beg; i < end; i++) {
        int s = g_csr[i];
        float p = __expf(lrelu(g_e2s[s] + ed));
        ssum += p;
        acc += p * g_h2[(size_t)s * 32 + lane];
    }
    out[(size_t)node * 32 + lane] = acc / (ssum + 1e-16f) + b2[lane];
}

// ---------------- launch ----------------
extern "C" void kernel_launch(void* const* d_in, const int* in_sizes, int n_in,
                              void* d_out, int out_size) {
    const float* x   = (const float*)d_in[0];
    const int*   ei  = (const int*)d_in[1];
    const float* W1  = (const float*)d_in[2];
    const float* as1 = (const float*)d_in[3];
    const float* ad1 = (const float*)d_in[4];
    const float* b1  = (const float*)d_in[5];
    const float* W2  = (const float*)d_in[6];
    const float* as2 = (const float*)d_in[7];
    const float* ad2 = (const float*)d_in[8];
    const float* b2  = (const float*)d_in[9];

    int Eo = in_sizes[1] / 2;
    if (Eo > EE) Eo = EE;
    int Et = Eo + NN;

    k_detect<<<1, 32>>>(ei);
    k_zero<<<(NN + 255) / 256, 256>>>();
    k_hist<<<(Et + 255) / 256, 256>>>(ei, Eo, Et);
    k_scan_a<<<NBLK, SCB>>>();
    k_scan_b<<<1, 128>>>();
    k_scan_c<<<NBLK, SCB>>>();
    k_fill<<<(Et + 255) / 256, 256>>>(ei, Eo, Et);

    dim3 g1((NN + 127) / 128, C1 / 64);
    k_gemm1<<<g1, 256>>>(x, W1);
    k_coef1<<<(NN * 32 + 255) / 256, 256>>>(as1, ad1);
    k_agg1c<<<(NN * 32 + 255) / 256, 256>>>(b1);

    k_gemm2<<<(NN + 63) / 64, 256>>>(W2);
    k_coef2<<<(NN + 255) / 256, 256>>>(as2, ad2);
    k_agg2c<<<(NN * 32 + 255) / 256, 256>>>((float*)d_out, b2);
}

// round 9
// speedup vs baseline: 3.5866x; 1.2608x over previous
#include <cuda_runtime.h>
#include <cuda_fp16.h>
#include <cstdint>

#define NN 100000
#define EE 1600000
#define ETOT (EE + NN)
#define C1 256          // HEADS*HID
#define HEADS 8
#define HID 32
#define NEG 0.2f
#define SCB 1024                      // scan chunk per block
#define NBLK ((NN + SCB - 1) / SCB)   // 98

// ---------------- scratch (static device allocations) ----------------
static __device__ __half2 g_xh [(size_t)NN * (C1 / 2)];  // layer1 projected (fp16)
static __device__ __half  g_x16[(size_t)NN * 128];       // x in fp16
static __device__ __half  g_w1h[128 * 256];              // W1 in fp16
static __device__ float g_e1s[NN * HEADS];
static __device__ float g_e1d[NN * HEADS];
static __device__ float g_h  [(size_t)NN * C1];   // relu(layer1 out)
static __device__ float g_h2 [NN * HID];          // layer2 projected
static __device__ float g_e2s[NN];
static __device__ float g_e2d[NN];
static __device__ int   g_deg[NN];
static __device__ int   g_rowptr[NN + 1];
static __device__ int   g_cursor[NN];
static __device__ int   g_csr[ETOT];              // src ids grouped by dst
static __device__ int   g_bsum[NBLK];
static __device__ int   g_boff[NBLK];
static __device__ int   g_is64;                   // edge_index dtype flag

// ---------------- helpers ----------------
__device__ __forceinline__ float lrelu(float x) { return x > 0.f ? x : NEG * x; }

__device__ __forceinline__ void edge_sd(const int* __restrict__ ei, int Eo,
                                        int e, int& s, int& d) {
    if (e < Eo) {
        if (g_is64) { s = ei[2 * e]; d = ei[2 * (Eo + e)]; }
        else        { s = ei[e];     d = ei[Eo + e]; }
    } else {
        s = e - Eo; d = s;   // self-loop
    }
}

// ---------------- dtype probe ----------------
__global__ void k_detect(const int* __restrict__ ei) {
    if (threadIdx.x == 0 && blockIdx.x == 0) {
        int all0 = 1;
        for (int i = 0; i < 128; i++)
            if (ei[2 * i + 1] != 0) { all0 = 0; break; }
        g_is64 = all0;
    }
}

// ---------------- CSR build ----------------
__global__ void k_zero() {
    int i = blockIdx.x * blockDim.x + threadIdx.x;
    if (i < NN) g_deg[i] = 0;
}

__global__ void k_hist(const int* __restrict__ ei, int Eo, int Et) {
    int e = blockIdx.x * blockDim.x + threadIdx.x;
    if (e >= Et) return;
    int s, d;
    edge_sd(ei, Eo, e, s, d);
    if ((unsigned)d >= NN) return;
    atomicAdd(&g_deg[d], 1);
}

__global__ void k_scan_a() {
    __shared__ int sh[32];
    int i = blockIdx.x * SCB + threadIdx.x;
    int v = (i < NN) ? g_deg[i] : 0;
#pragma unroll
    for (int o = 16; o > 0; o >>= 1) v += __shfl_down_sync(0xffffffffu, v, o);
    if ((threadIdx.x & 31) == 0) sh[threadIdx.x >> 5] = v;
    __syncthreads();
    if (threadIdx.x < 32) {
        int w = (threadIdx.x < (SCB / 32)) ? sh[threadIdx.x] : 0;
#pragma unroll
        for (int o = 16; o > 0; o >>= 1) w += __shfl_down_sync(0xffffffffu, w, o);
        if (threadIdx.x == 0) g_bsum[blockIdx.x] = w;
    }
}

__global__ void k_scan_b() {
    __shared__ int sh[NBLK];
    int t = threadIdx.x;
    if (t < NBLK) sh[t] = g_bsum[t];
    __syncthreads();
    if (t == 0) {
        int run = 0;
        for (int b = 0; b < NBLK; b++) { int v = sh[b]; sh[b] = run; run += v; }
        g_rowptr[NN] = run;
    }
    __syncthreads();
    if (t < NBLK) g_boff[t] = sh[t];
}

__global__ void k_scan_c() {
    __shared__ int sh[SCB];
    int t = threadIdx.x;
    int i = blockIdx.x * SCB + t;
    sh[t] = (i < NN) ? g_deg[i] : 0;
    __syncthreads();
#pragma unroll
    for (int off = 1; off < SCB; off <<= 1) {
        int v = (t >= off) ? sh[t - off] : 0;
        __syncthreads();
        sh[t] += v;
        __syncthreads();
    }
    if (i < NN) {
        int excl = g_boff[blockIdx.x] + sh[t] - g_deg[i];
        g_rowptr[i] = excl;
        g_cursor[i] = excl;
    }
}

__global__ void k_fill(const int* __restrict__ ei, int Eo, int Et) {
    int e = blockIdx.x * blockDim.x + threadIdx.x;
    if (e >= Et) return;
    int s, d;
    edge_sd(ei, Eo, e, s, d);
    if ((unsigned)s >= NN || (unsigned)d >= NN) return;
    int pos = atomicAdd(&g_cursor[d], 1);
    g_csr[pos] = s;
}

// ---------------- fp16 conversions ----------------
__global__ void k_cvtx(const float* __restrict__ x) {
    size_t i = ((size_t)blockIdx.x * blockDim.x + threadIdx.x) * 8;
    if (i >= (size_t)NN * 128) return;
    float4 v0 = *(const float4*)(x + i);
    float4 v1 = *(const float4*)(x + i + 4);
    __half2 h[4];
    h[0] = __floats2half2_rn(v0.x, v0.y);
    h[1] = __floats2half2_rn(v0.z, v0.w);
    h[2] = __floats2half2_rn(v1.x, v1.y);
    h[3] = __floats2half2_rn(v1.z, v1.w);
    *(uint4*)(g_x16 + i) = *(uint4*)h;
}

__global__ void k_cvtw(const float* __restrict__ W1) {
    int i = (blockIdx.x * blockDim.x + threadIdx.x) * 8;
    if (i >= 128 * 256) return;
    float4 v0 = *(const float4*)(W1 + i);
    float4 v1 = *(const float4*)(W1 + i + 4);
    __half2 h[4];
    h[0] = __floats2half2_rn(v0.x, v0.y);
    h[1] = __floats2half2_rn(v0.z, v0.w);
    h[2] = __floats2half2_rn(v1.x, v1.y);
    h[3] = __floats2half2_rn(v1.z, v1.w);
    *(uint4*)(g_w1h + i) = *(uint4*)h;
}

// ---------------- GEMM1 (tensor cores): xh = x16[N,128] @ w1h[128,256] ----------------
// BM=128, BN=64, 8 warps (4m x 2n), warp tile 32x32, mma.m16n8k16 fp16->fp32.
#define AS_STRIDE 24   // halves per As row (16 + 8 pad)
#define BS_STRIDE 72   // halves per Bs row (64 + 8 pad)
__global__ void k_gemm1tc() {
    __shared__ __half As[128 * AS_STRIDE];
    __shared__ __half Bs[16 * BS_STRIDE];
    int tid = threadIdx.x;
    int lane = tid & 31;
    int wid = tid >> 5;              // 0..7
    int warp_m = wid & 3;            // 4 m-warps
    int warp_n = wid >> 2;           // 2 n-warps
    int r0 = blockIdx.x * 128;
    int c0 = blockIdx.y * 64;

    float acc[2][4][4];
#pragma unroll
    for (int mb = 0; mb < 2; mb++)
#pragma unroll
        for (int nb = 0; nb < 4; nb++)
#pragma unroll
            for (int f = 0; f < 4; f++) acc[mb][nb][f] = 0.f;

    // ldmatrix source addresses (computed once; k-step adds col offset)
    int amat = lane >> 3, amrow = lane & 7;
    int a_row_base[2], a_col;
    a_col = (amat >> 1) * 8;
#pragma unroll
    for (int mb = 0; mb < 2; mb++)
        a_row_base[mb] = warp_m * 32 + mb * 16 + (amat & 1) * 8 + amrow;
    int b_k = lane & 15;   // lanes 16-31 duplicate (ignored by x2)

    for (int k0 = 0; k0 < 128; k0 += 16) {
        // load A tile: 128 rows x 16 halves; 256 threads x 16B
        {
            int row = tid >> 1;
            int off = (tid & 1) * 8;
            int gr = r0 + row;
            uint4 v = make_uint4(0u, 0u, 0u, 0u);
            if (gr < NN) v = *(const uint4*)(g_x16 + (size_t)gr * 128 + k0 + off);
            *(uint4*)(As + row * AS_STRIDE + off) = v;
        }
        // load B tile: 16 rows x 64 halves; 256 threads x 8B
        {
            int row = tid >> 4;
            int off = (tid & 15) * 4;
            uint2 v = *(const uint2*)(g_w1h + (size_t)(k0 + row) * 256 + c0 + off);
            *(uint2*)(Bs + row * BS_STRIDE + off) = v;
        }
        __syncthreads();

        unsigned a[2][4], b[4][2];
#pragma unroll
        for (int mb = 0; mb < 2; mb++) {
            unsigned addr = (unsigned)__cvta_generic_to_shared(
                As + a_row_base[mb] * AS_STRIDE + a_col);
            asm volatile("ldmatrix.sync.aligned.m8n8.x4.shared.b16 {%0,%1,%2,%3}, [%4];"
                         : "=r"(a[mb][0]), "=r"(a[mb][1]), "=r"(a[mb][2]), "=r"(a[mb][3])
                         : "r"(addr));
        }
#pragma unroll
        for (int nb = 0; nb < 4; nb++) {
            unsigned addr = (unsigned)__cvta_generic_to_shared(
                Bs + b_k * BS_STRIDE + warp_n * 32 + nb * 8);
            asm volatile("ldmatrix.sync.aligned.m8n8.x2.trans.shared.b16 {%0,%1}, [%2];"
                         : "=r"(b[nb][0]), "=r"(b[nb][1]) : "r"(addr));
        }
#pragma unroll
        for (int mb = 0; mb < 2; mb++)
#pragma unroll
            for (int nb = 0; nb < 4; nb++) {
                asm volatile(
                    "mma.sync.aligned.m16n8k16.row.col.f32.f16.f16.f32 "
                    "{%0,%1,%2,%3},{%4,%5,%6,%7},{%8,%9},{%0,%1,%2,%3};"
                    : "+f"(acc[mb][nb][0]), "+f"(acc[mb][nb][1]),
                      "+f"(acc[mb][nb][2]), "+f"(acc[mb][nb][3])
                    : "r"(a[mb][0]), "r"(a[mb][1]), "r"(a[mb][2]), "r"(a[mb][3]),
                      "r"(b[nb][0]), "r"(b[nb][1]));
            }
        __syncthreads();
    }

    // epilogue: write fp16 to g_xh
#pragma unroll
    for (int mb = 0; mb < 2; mb++) {
        int row_lo = r0 + warp_m * 32 + mb * 16 + (lane >> 2);
        int row_hi = row_lo + 8;
#pragma unroll
        for (int nb = 0; nb < 4; nb++) {
            int c2 = (c0 >> 1) + warp_n * 16 + nb * 4 + (lane & 3);  // half2 index
            if (row_lo < NN)
                g_xh[(size_t)row_lo * (C1 / 2) + c2] =
                    __floats2half2_rn(acc[mb][nb][0], acc[mb][nb][1]);
            if (row_hi < NN)
                g_xh[(size_t)row_hi * (C1 / 2) + c2] =
                    __floats2half2_rn(acc[mb][nb][2], acc[mb][nb][3]);
        }
    }
}

// ---------------- attention coefficients, layer 1 (warp per node) ----------------
__global__ void k_coef1(const float* __restrict__ as, const float* __restrict__ ad) {
    int w = (blockIdx.x * blockDim.x + threadIdx.x) >> 5;
    int lane = threadIdx.x & 31;
    if (w >= NN) return;
    float4 raw = ((const float4*)(g_xh + (size_t)w * (C1 / 2)))[lane];
    const __half2* hp = (const __half2*)&raw;
    float2 q0 = __half22float2(hp[0]), q1 = __half22float2(hp[1]);
    float2 q2 = __half22float2(hp[2]), q3 = __half22float2(hp[3]);
    const float4* a4 = (const float4*)as;
    const float4* d4 = (const float4*)ad;
    float4 s0 = a4[lane * 2], s1v = a4[lane * 2 + 1];
    float4 d0 = d4[lane * 2], d1v = d4[lane * 2 + 1];
    float ps = q0.x * s0.x + q0.y * s0.y + q1.x * s0.z + q1.y * s0.w
             + q2.x * s1v.x + q2.y * s1v.y + q3.x * s1v.z + q3.y * s1v.w;
    float pd = q0.x * d0.x + q0.y * d0.y + q1.x * d0.z + q1.y * d0.w
             + q2.x * d1v.x + q2.y * d1v.y + q3.x * d1v.z + q3.y * d1v.w;
    ps += __shfl_xor_sync(0xffffffffu, ps, 1);
    ps += __shfl_xor_sync(0xffffffffu, ps, 2);
    pd += __shfl_xor_sync(0xffffffffu, pd, 1);
    pd += __shfl_xor_sync(0xffffffffu, pd, 2);
    if ((lane & 3) == 0) {
        g_e1s[w * 8 + (lane >> 2)] = ps;
        g_e1d[w * 8 + (lane >> 2)] = pd;
    }
}

// ---------------- layer-1 CSR aggregate + finalize (warp per node) ----------------
__global__ void k_agg1c(const float* __restrict__ b1) {
    int node = (blockIdx.x * blockDim.x + threadIdx.x) >> 5;
    int lane = threadIdx.x & 31;
    if (node >= NN) return;
    int beg = g_rowptr[node], end = g_rowptr[node + 1];
    int h = lane >> 2;
    float ed = g_e1d[node * 8 + h];
    float a0 = 0.f, a1 = 0.f, a2 = 0.f, a3 = 0.f;
    float a4 = 0.f, a5 = 0.f, a6 = 0.f, a7 = 0.f;
    float ssum = 0.f;
    for (int i = beg; i < end; i++) {
        int s = g_csr[i];
        float p = __expf(lrelu(g_e1s[s * 8 + h] + ed));
        ssum += p;
        float4 raw = ((const float4*)(g_xh + (size_t)s * (C1 / 2)))[lane];
        const __half2* hp = (const __half2*)&raw;
        float2 q0 = __half22float2(hp[0]), q1 = __half22float2(hp[1]);
        float2 q2 = __half22float2(hp[2]), q3 = __half22float2(hp[3]);
        a0 += p * q0.x; a1 += p * q0.y; a2 += p * q1.x; a3 += p * q1.y;
        a4 += p * q2.x; a5 += p * q2.y; a6 += p * q3.x; a7 += p * q3.y;
    }
    float inv = 1.f / (ssum + 1e-16f);
    const float4* bb = (const float4*)(b1 + lane * 8);
    float4 b0 = bb[0], b1v = bb[1];
    float4 o0, o1;
    o0.x = fmaxf(a0 * inv + b0.x, 0.f);  o0.y = fmaxf(a1 * inv + b0.y, 0.f);
    o0.z = fmaxf(a2 * inv + b0.z, 0.f);  o0.w = fmaxf(a3 * inv + b0.w, 0.f);
    o1.x = fmaxf(a4 * inv + b1v.x, 0.f); o1.y = fmaxf(a5 * inv + b1v.y, 0.f);
    o1.z = fmaxf(a6 * inv + b1v.z, 0.f); o1.w = fmaxf(a7 * inv + b1v.w, 0.f);
    float4* dst = (float4*)(g_h + (size_t)node * 256 + lane * 8);
    dst[0] = o0;
    dst[1] = o1;
}

// ---------------- GEMM2: h2 = h[N,256] @ W2[256,32] ----------------
__global__ void k_gemm2(const float* __restrict__ W2) {
    __shared__ float hs[32 * 64];
    __shared__ float ws[32 * 32];
    int tid = threadIdx.x;
    int r0 = blockIdx.x * 64;
    int tx = tid & 7;
    int ty = tid >> 3;
    float acc[2][4];
#pragma unroll
    for (int i = 0; i < 2; i++)
#pragma unroll
        for (int j = 0; j < 4; j++) acc[i][j] = 0.f;

    for (int k0 = 0; k0 < 256; k0 += 32) {
#pragma unroll
        for (int i = 0; i < 2; i++) {
            int f = tid + i * 256;
            int row = f >> 3;
            int kq = f & 7;
            int gr = r0 + row;
            float4 v = make_float4(0.f, 0.f, 0.f, 0.f);
            if (gr < NN) v = *(const float4*)(g_h + (size_t)gr * 256 + k0 + kq * 4);
            hs[(kq * 4 + 0) * 64 + row] = v.x;
            hs[(kq * 4 + 1) * 64 + row] = v.y;
            hs[(kq * 4 + 2) * 64 + row] = v.z;
            hs[(kq * 4 + 3) * 64 + row] = v.w;
        }
        {
            int k = tid >> 3;
            int cq = tid & 7;
            *(float4*)(ws + k * 32 + cq * 4) =
                *(const float4*)(W2 + (size_t)(k0 + k) * 32 + cq * 4);
        }
        __syncthreads();
#pragma unroll
        for (int kk = 0; kk < 32; kk++) {
            float2 a = *(float2*)(hs + kk * 64 + ty * 2);
            float4 b = *(float4*)(ws + kk * 32 + tx * 4);
            acc[0][0] += a.x * b.x; acc[0][1] += a.x * b.y;
            acc[0][2] += a.x * b.z; acc[0][3] += a.x * b.w;
            acc[1][0] += a.y * b.x; acc[1][1] += a.y * b.y;
            acc[1][2] += a.y * b.z; acc[1][3] += a.y * b.w;
        }
        __syncthreads();
    }
#pragma unroll
    for (int i = 0; i < 2; i++) {
        int gr = r0 + ty * 2 + i;
        if (gr < NN)
            *(float4*)(g_h2 + (size_t)gr * 32 + tx * 4) =
                make_float4(acc[i][0], acc[i][1], acc[i][2], acc[i][3]);
    }
}

// ---------------- coefficients, layer 2 (thread per node) ----------------
__global__ void k_coef2(const float* __restrict__ as, const float* __restrict__ ad) {
    int n = blockIdx.x * blockDim.x + threadIdx.x;
    if (n >= NN) return;
    const float4* h4 = (const float4*)(g_h2 + (size_t)n * 32);
    float ps = 0.f, pd = 0.f;
#pragma unroll
    for (int j = 0; j < 8; j++) {
        float4 v = h4[j];
        float4 a = ((const float4*)as)[j];
        float4 b = ((const float4*)ad)[j];
        ps += v.x * a.x + v.y * a.y + v.z * a.z + v.w * a.w;
        pd += v.x * b.x + v.y * b.y + v.z * b.z + v.w * b.w;
    }
    g_e2s[n] = ps;
    g_e2d[n] = pd;
}

// ---------------- layer-2 CSR aggregate + finalize (warp per node) ----------------
__global__ void k_agg2c(float* __restrict__ out, const float* __restrict__ b2) {
    int node = (blockIdx.x * blockDim.x + threadIdx.x) >> 5;
    int lane = threadIdx.x & 31;
    if (node >= NN) return;
    int beg = g_rowptr[node], end = g_rowptr[node + 1];
    float ed = g_e2d[node];
    float acc = 0.f, ssum = 0.f;
    for (int i = beg; i < end; i++) {
        int s = g_csr[i];
        float p = __expf(lrelu(g_e2s[s] + ed));
        ssum += p;
        acc += p * g_h2[(size_t)s * 32 + lane];
    }
    out[(size_t)node * 32 + lane] = acc / (ssum + 1e-16f) + b2[lane];
}

// ---------------- launch ----------------
extern "C" void kernel_launch(void* const* d_in, const int* in_sizes, int n_in,
                              void* d_out, int out_size) {
    const float* x   = (const float*)d_in[0];
    const int*   ei  = (const int*)d_in[1];
    const float* W1  = (const float*)d_in[2];
    const float* as1 = (const float*)d_in[3];
    const float* ad1 = (const float*)d_in[4];
    const float* b1  = (const float*)d_in[5];
    const float* W2  = (const float*)d_in[6];
    const float* as2 = (const float*)d_in[7];
    const float* ad2 = (const float*)d_in[8];
    const float* b2  = (const float*)d_in[9];

    int Eo = in_sizes[1] / 2;
    if (Eo > EE) Eo = EE;
    int Et = Eo + NN;

    k_detect<<<1, 32>>>(ei);
    k_zero<<<(NN + 255) / 256, 256>>>();
    k_hist<<<(Et + 255) / 256, 256>>>(ei, Eo, Et);
    k_scan_a<<<NBLK, SCB>>>();
    k_scan_b<<<1, 128>>>();
    k_scan_c<<<NBLK, SCB>>>();
    k_fill<<<(Et + 255) / 256, 256>>>(ei, Eo, Et);

    k_cvtx<<<(NN * 128 / 8 + 255) / 256, 256>>>(x);
    k_cvtw<<<(128 * 256 / 8 + 63) / 64, 64>>>(W1);
    dim3 g1((NN + 127) / 128, C1 / 64);
    k_gemm1tc<<<g1, 256>>>();
    k_coef1<<<(NN * 32 + 255) / 256, 256>>>(as1, ad1);
    k_agg1c<<<(NN * 32 + 255) / 256, 256>>>(b1);

    k_gemm2<<<(NN + 63) / 64, 256>>>(W2);
    k_coef2<<<(NN + 255) / 256, 256>>>(as2, ad2);
    k_agg2c<<<(NN * 32 + 255) / 256, 256>>>((float*)d_out, b2);
}

// round 12
// speedup vs baseline: 4.4294x; 1.2350x over previous
#include <cuda_runtime.h>
#include <cuda_fp16.h>
#include <cstdint>

#define NN 100000
#define EE 1600000
#define ETOT (EE + NN)
#define C1 256          // HEADS*HID
#define HEADS 8
#define HID 32
#define NEG 0.2f
#define SCB 1024                      // scan chunk per block
#define NBLK ((NN + SCB - 1) / SCB)   // 98

// ---------------- scratch (static device allocations) ----------------
static __device__ __half2 g_xh [(size_t)NN * (C1 / 2)];  // layer1 projected (fp16)
static __device__ __half  g_x16[(size_t)NN * 128];       // x in fp16
static __device__ __half  g_w1h[128 * 256];              // W1 in fp16
static __device__ __half  g_w2h[256 * 32];               // W2 in fp16
static __device__ float g_e1s[NN * HEADS];
static __device__ float g_e1d[NN * HEADS];
static __device__ __half g_hh[(size_t)NN * C1];   // relu(layer1 out), fp16
static __device__ float g_h2 [NN * HID];          // layer2 projected (fp32)
static __device__ float g_e2s[NN];
static __device__ float g_e2d[NN];
static __device__ int   g_deg[NN];
static __device__ int   g_rowptr[NN + 1];
static __device__ int   g_cursor[NN];
static __device__ int   g_csr[ETOT];              // src ids grouped by dst
static __device__ int   g_bsum[NBLK];
static __device__ int   g_boff[NBLK];
static __device__ int   g_is64;                   // edge_index dtype flag

// ---------------- helpers ----------------
__device__ __forceinline__ float lrelu(float x) { return x > 0.f ? x : NEG * x; }

__device__ __forceinline__ void edge_sd(const int* __restrict__ ei, int Eo,
                                        int e, int& s, int& d) {
    if (e < Eo) {
        if (g_is64) { s = ei[2 * e]; d = ei[2 * (Eo + e)]; }
        else        { s = ei[e];     d = ei[Eo + e]; }
    } else {
        s = e - Eo; d = s;   // self-loop
    }
}

// ---------------- dtype probe ----------------
__global__ void k_detect(const int* __restrict__ ei) {
    if (threadIdx.x == 0 && blockIdx.x == 0) {
        int all0 = 1;
        for (int i = 0; i < 128; i++)
            if (ei[2 * i + 1] != 0) { all0 = 0; break; }
        g_is64 = all0;
    }
}

// ---------------- CSR build ----------------
__global__ void k_zero() {
    int i = blockIdx.x * blockDim.x + threadIdx.x;
    if (i < NN) g_deg[i] = 0;
}

__global__ void k_hist(const int* __restrict__ ei, int Eo, int Et) {
    int e = blockIdx.x * blockDim.x + threadIdx.x;
    if (e >= Et) return;
    int s, d;
    edge_sd(ei, Eo, e, s, d);
    if ((unsigned)d >= NN) return;
    atomicAdd(&g_deg[d], 1);
}

__global__ void k_scan_a() {
    __shared__ int sh[32];
    int i = blockIdx.x * SCB + threadIdx.x;
    int v = (i < NN) ? g_deg[i] : 0;
#pragma unroll
    for (int o = 16; o > 0; o >>= 1) v += __shfl_down_sync(0xffffffffu, v, o);
    if ((threadIdx.x & 31) == 0) sh[threadIdx.x >> 5] = v;
    __syncthreads();
    if (threadIdx.x < 32) {
        int w = (threadIdx.x < (SCB / 32)) ? sh[threadIdx.x] : 0;
#pragma unroll
        for (int o = 16; o > 0; o >>= 1) w += __shfl_down_sync(0xffffffffu, w, o);
        if (threadIdx.x == 0) g_bsum[blockIdx.x] = w;
    }
}

__global__ void k_scan_b() {
    __shared__ int sh[NBLK];
    int t = threadIdx.x;
    if (t < NBLK) sh[t] = g_bsum[t];
    __syncthreads();
    if (t == 0) {
        int run = 0;
        for (int b = 0; b < NBLK; b++) { int v = sh[b]; sh[b] = run; run += v; }
        g_rowptr[NN] = run;
    }
    __syncthreads();
    if (t < NBLK) g_boff[t] = sh[t];
}

__global__ void k_scan_c() {
    __shared__ int sh[SCB];
    int t = threadIdx.x;
    int i = blockIdx.x * SCB + t;
    sh[t] = (i < NN) ? g_deg[i] : 0;
    __syncthreads();
#pragma unroll
    for (int off = 1; off < SCB; off <<= 1) {
        int v = (t >= off) ? sh[t - off] : 0;
        __syncthreads();
        sh[t] += v;
        __syncthreads();
    }
    if (i < NN) {
        int excl = g_boff[blockIdx.x] + sh[t] - g_deg[i];
        g_rowptr[i] = excl;
        g_cursor[i] = excl;
    }
}

__global__ void k_fill(const int* __restrict__ ei, int Eo, int Et) {
    int e = blockIdx.x * blockDim.x + threadIdx.x;
    if (e >= Et) return;
    int s, d;
    edge_sd(ei, Eo, e, s, d);
    if ((unsigned)s >= NN || (unsigned)d >= NN) return;
    int pos = atomicAdd(&g_cursor[d], 1);
    g_csr[pos] = s;
}

// ---------------- fp16 conversions ----------------
__global__ void k_cvtx(const float* __restrict__ x) {
    size_t i = ((size_t)blockIdx.x * blockDim.x + threadIdx.x) * 8;
    if (i >= (size_t)NN * 128) return;
    float4 v0 = *(const float4*)(x + i);
    float4 v1 = *(const float4*)(x + i + 4);
    __half2 h[4];
    h[0] = __floats2half2_rn(v0.x, v0.y);
    h[1] = __floats2half2_rn(v0.z, v0.w);
    h[2] = __floats2half2_rn(v1.x, v1.y);
    h[3] = __floats2half2_rn(v1.z, v1.w);
    *(uint4*)(g_x16 + i) = *(uint4*)h;
}

__global__ void k_cvtw(const float* __restrict__ W1) {
    int i = (blockIdx.x * blockDim.x + threadIdx.x) * 8;
    if (i >= 128 * 256) return;
    float4 v0 = *(const float4*)(W1 + i);
    float4 v1 = *(const float4*)(W1 + i + 4);
    __half2 h[4];
    h[0] = __floats2half2_rn(v0.x, v0.y);
    h[1] = __floats2half2_rn(v0.z, v0.w);
    h[2] = __floats2half2_rn(v1.x, v1.y);
    h[3] = __floats2half2_rn(v1.z, v1.w);
    *(uint4*)(g_w1h + i) = *(uint4*)h;
}

__global__ void k_cvtw2(const float* __restrict__ W2) {
    int i = (blockIdx.x * blockDim.x + threadIdx.x) * 8;
    if (i >= 256 * 32) return;
    float4 v0 = *(const float4*)(W2 + i);
    float4 v1 = *(const float4*)(W2 + i + 4);
    __half2 h[4];
    h[0] = __floats2half2_rn(v0.x, v0.y);
    h[1] = __floats2half2_rn(v0.z, v0.w);
    h[2] = __floats2half2_rn(v1.x, v1.y);
    h[3] = __floats2half2_rn(v1.z, v1.w);
    *(uint4*)(g_w2h + i) = *(uint4*)h;
}

// ---------------- GEMM1 (tensor cores): xh = x16[N,128] @ w1h[128,256] ----------------
#define AS_STRIDE 24   // halves per As row (16 + 8 pad)
#define BS_STRIDE 72   // halves per Bs row (64 + 8 pad)
__global__ void k_gemm1tc() {
    __shared__ __half As[128 * AS_STRIDE];
    __shared__ __half Bs[16 * BS_STRIDE];
    int tid = threadIdx.x;
    int lane = tid & 31;
    int wid = tid >> 5;              // 0..7
    int warp_m = wid & 3;            // 4 m-warps
    int warp_n = wid >> 2;           // 2 n-warps
    int r0 = blockIdx.x * 128;
    int c0 = blockIdx.y * 64;

    float acc[2][4][4];
#pragma unroll
    for (int mb = 0; mb < 2; mb++)
#pragma unroll
        for (int nb = 0; nb < 4; nb++)
#pragma unroll
            for (int f = 0; f < 4; f++) acc[mb][nb][f] = 0.f;

    int amat = lane >> 3, amrow = lane & 7;
    int a_row_base[2], a_col;
    a_col = (amat >> 1) * 8;
#pragma unroll
    for (int mb = 0; mb < 2; mb++)
        a_row_base[mb] = warp_m * 32 + mb * 16 + (amat & 1) * 8 + amrow;
    int b_k = lane & 15;

    for (int k0 = 0; k0 < 128; k0 += 16) {
        {
            int row = tid >> 1;
            int off = (tid & 1) * 8;
            int gr = r0 + row;
            uint4 v = make_uint4(0u, 0u, 0u, 0u);
            if (gr < NN) v = *(const uint4*)(g_x16 + (size_t)gr * 128 + k0 + off);
            *(uint4*)(As + row * AS_STRIDE + off) = v;
        }
        {
            int row = tid >> 4;
            int off = (tid & 15) * 4;
            uint2 v = *(const uint2*)(g_w1h + (size_t)(k0 + row) * 256 + c0 + off);
            *(uint2*)(Bs + row * BS_STRIDE + off) = v;
        }
        __syncthreads();

        unsigned a[2][4], b[4][2];
#pragma unroll
        for (int mb = 0; mb < 2; mb++) {
            unsigned addr = (unsigned)__cvta_generic_to_shared(
                As + a_row_base[mb] * AS_STRIDE + a_col);
            asm volatile("ldmatrix.sync.aligned.m8n8.x4.shared.b16 {%0,%1,%2,%3}, [%4];"
                         : "=r"(a[mb][0]), "=r"(a[mb][1]), "=r"(a[mb][2]), "=r"(a[mb][3])
                         : "r"(addr));
        }
#pragma unroll
        for (int nb = 0; nb < 4; nb++) {
            unsigned addr = (unsigned)__cvta_generic_to_shared(
                Bs + b_k * BS_STRIDE + warp_n * 32 + nb * 8);
            asm volatile("ldmatrix.sync.aligned.m8n8.x2.trans.shared.b16 {%0,%1}, [%2];"
                         : "=r"(b[nb][0]), "=r"(b[nb][1]) : "r"(addr));
        }
#pragma unroll
        for (int mb = 0; mb < 2; mb++)
#pragma unroll
            for (int nb = 0; nb < 4; nb++) {
                asm volatile(
                    "mma.sync.aligned.m16n8k16.row.col.f32.f16.f16.f32 "
                    "{%0,%1,%2,%3},{%4,%5,%6,%7},{%8,%9},{%0,%1,%2,%3};"
                    : "+f"(acc[mb][nb][0]), "+f"(acc[mb][nb][1]),
                      "+f"(acc[mb][nb][2]), "+f"(acc[mb][nb][3])
                    : "r"(a[mb][0]), "r"(a[mb][1]), "r"(a[mb][2]), "r"(a[mb][3]),
                      "r"(b[nb][0]), "r"(b[nb][1]));
            }
        __syncthreads();
    }

#pragma unroll
    for (int mb = 0; mb < 2; mb++) {
        int row_lo = r0 + warp_m * 32 + mb * 16 + (lane >> 2);
        int row_hi = row_lo + 8;
#pragma unroll
        for (int nb = 0; nb < 4; nb++) {
            int c2 = (c0 >> 1) + warp_n * 16 + nb * 4 + (lane & 3);  // half2 index
            if (row_lo < NN)
                g_xh[(size_t)row_lo * (C1 / 2) + c2] =
                    __floats2half2_rn(acc[mb][nb][0], acc[mb][nb][1]);
            if (row_hi < NN)
                g_xh[(size_t)row_hi * (C1 / 2) + c2] =
                    __floats2half2_rn(acc[mb][nb][2], acc[mb][nb][3]);
        }
    }
}

// ---------------- attention coefficients, layer 1 (warp per node) ----------------
__global__ void k_coef1(const float* __restrict__ as, const float* __restrict__ ad) {
    int w = (blockIdx.x * blockDim.x + threadIdx.x) >> 5;
    int lane = threadIdx.x & 31;
    if (w >= NN) return;
    float4 raw = ((const float4*)(g_xh + (size_t)w * (C1 / 2)))[lane];
    const __half2* hp = (const __half2*)&raw;
    float2 q0 = __half22float2(hp[0]), q1 = __half22float2(hp[1]);
    float2 q2 = __half22float2(hp[2]), q3 = __half22float2(hp[3]);
    const float4* a4 = (const float4*)as;
    const float4* d4 = (const float4*)ad;
    float4 s0 = a4[lane * 2], s1v = a4[lane * 2 + 1];
    float4 d0 = d4[lane * 2], d1v = d4[lane * 2 + 1];
    float ps = q0.x * s0.x + q0.y * s0.y + q1.x * s0.z + q1.y * s0.w
             + q2.x * s1v.x + q2.y * s1v.y + q3.x * s1v.z + q3.y * s1v.w;
    float pd = q0.x * d0.x + q0.y * d0.y + q1.x * d0.z + q1.y * d0.w
             + q2.x * d1v.x + q2.y * d1v.y + q3.x * d1v.z + q3.y * d1v.w;
    ps += __shfl_xor_sync(0xffffffffu, ps, 1);
    ps += __shfl_xor_sync(0xffffffffu, ps, 2);
    pd += __shfl_xor_sync(0xffffffffu, pd, 1);
    pd += __shfl_xor_sync(0xffffffffu, pd, 2);
    if ((lane & 3) == 0) {
        g_e1s[w * 8 + (lane >> 2)] = ps;
        g_e1d[w * 8 + (lane >> 2)] = pd;
    }
}

// ---------------- layer-1 CSR aggregate + finalize (warp per node) ----------------
__global__ void k_agg1c(const float* __restrict__ b1) {
    int node = (blockIdx.x * blockDim.x + threadIdx.x) >> 5;
    int lane = threadIdx.x & 31;
    if (node >= NN) return;
    int beg = g_rowptr[node], end = g_rowptr[node + 1];
    int h = lane >> 2;
    float ed = g_e1d[node * 8 + h];
    float a0 = 0.f, a1 = 0.f, a2 = 0.f, a3 = 0.f;
    float a4 = 0.f, a5 = 0.f, a6 = 0.f, a7 = 0.f;
    float ssum = 0.f;
    for (int i = beg; i < end; i++) {
        int s = g_csr[i];
        float p = __expf(lrelu(g_e1s[s * 8 + h] + ed));
        ssum += p;
        float4 raw = ((const float4*)(g_xh + (size_t)s * (C1 / 2)))[lane];
        const __half2* hp = (const __half2*)&raw;
        float2 q0 = __half22float2(hp[0]), q1 = __half22float2(hp[1]);
        float2 q2 = __half22float2(hp[2]), q3 = __half22float2(hp[3]);
        a0 += p * q0.x; a1 += p * q0.y; a2 += p * q1.x; a3 += p * q1.y;
        a4 += p * q2.x; a5 += p * q2.y; a6 += p * q3.x; a7 += p * q3.y;
    }
    float inv = 1.f / (ssum + 1e-16f);
    const float4* bb = (const float4*)(b1 + lane * 8);
    float4 b0 = bb[0], b1v = bb[1];
    __half2 ho[4];
    ho[0] = __floats2half2_rn(fmaxf(a0 * inv + b0.x, 0.f),  fmaxf(a1 * inv + b0.y, 0.f));
    ho[1] = __floats2half2_rn(fmaxf(a2 * inv + b0.z, 0.f),  fmaxf(a3 * inv + b0.w, 0.f));
    ho[2] = __floats2half2_rn(fmaxf(a4 * inv + b1v.x, 0.f), fmaxf(a5 * inv + b1v.y, 0.f));
    ho[3] = __floats2half2_rn(fmaxf(a6 * inv + b1v.z, 0.f), fmaxf(a7 * inv + b1v.w, 0.f));
    *(uint4*)(g_hh + (size_t)node * 256 + lane * 8) = *(uint4*)ho;
}

// ---------------- GEMM2 (tensor cores): h2 = hh[N,256] @ w2h[256,32] ----------------
// BM=128, BN=32(full), 8 warps each 16 rows; whole B resident in smem.
// BS2=40 halves (80 B/row): 16B-aligned rows for uint4 fill, conflict-free trans-ldmatrix.
#define BS2 40
__global__ void k_gemm2tc() {
    __shared__ __half As[128 * AS_STRIDE];
    __shared__ __half Bs[256 * BS2];
    int tid = threadIdx.x;
    int lane = tid & 31;
    int wid = tid >> 5;              // 0..7, warp owns rows [wid*16, +16)
    int r0 = blockIdx.x * 128;

    // load all of W2 (256x32 fp16) into smem
    for (int i = tid; i < 1024; i += 256) {      // 1024 uint4 = 8192 halves
        int row = i >> 2;
        int off = (i & 3) * 8;
        *(uint4*)(Bs + row * BS2 + off) = *(const uint4*)(g_w2h + row * 32 + off);
    }

    float acc[4][4];
#pragma unroll
    for (int nb = 0; nb < 4; nb++)
#pragma unroll
        for (int f = 0; f < 4; f++) acc[nb][f] = 0.f;

    int amat = lane >> 3, amrow = lane & 7;
    int a_row = wid * 16 + (amat & 1) * 8 + amrow;
    int a_col = (amat >> 1) * 8;
    int b_k = lane & 15;
    __syncthreads();

    for (int k0 = 0; k0 < 256; k0 += 16) {
        {
            int row = tid >> 1;
            int off = (tid & 1) * 8;
            int gr = r0 + row;
            uint4 v = make_uint4(0u, 0u, 0u, 0u);
            if (gr < NN) v = *(const uint4*)(g_hh + (size_t)gr * 256 + k0 + off);
            *(uint4*)(As + row * AS_STRIDE + off) = v;
        }
        __syncthreads();

        unsigned a[4];
        {
            unsigned addr = (unsigned)__cvta_generic_to_shared(
                As + a_row * AS_STRIDE + a_col);
            asm volatile("ldmatrix.sync.aligned.m8n8.x4.shared.b16 {%0,%1,%2,%3}, [%4];"
                         : "=r"(a[0]), "=r"(a[1]), "=r"(a[2]), "=r"(a[3]) : "r"(addr));
        }
#pragma unroll
        for (int nb = 0; nb < 4; nb++) {
            unsigned b0r, b1r;
            unsigned addr = (unsigned)__cvta_generic_to_shared(
                Bs + (k0 + b_k) * BS2 + nb * 8);
            asm volatile("ldmatrix.sync.aligned.m8n8.x2.trans.shared.b16 {%0,%1}, [%2];"
                         : "=r"(b0r), "=r"(b1r) : "r"(addr));
            asm volatile(
                "mma.sync.aligned.m16n8k16.row.col.f32.f16.f16.f32 "
                "{%0,%1,%2,%3},{%4,%5,%6,%7},{%8,%9},{%0,%1,%2,%3};"
                : "+f"(acc[nb][0]), "+f"(acc[nb][1]), "+f"(acc[nb][2]), "+f"(acc[nb][3])
                : "r"(a[0]), "r"(a[1]), "r"(a[2]), "r"(a[3]), "r"(b0r), "r"(b1r));
        }
        __syncthreads();
    }

    // epilogue: fp32 to g_h2
    int row_lo = r0 + wid * 16 + (lane >> 2);
    int row_hi = row_lo + 8;
#pragma unroll
    for (int nb = 0; nb < 4; nb++) {
        int col = nb * 8 + 2 * (lane & 3);
        if (row_lo < NN)
            *(float2*)(g_h2 + (size_t)row_lo * 32 + col) =
                make_float2(acc[nb][0], acc[nb][1]);
        if (row_hi < NN)
            *(float2*)(g_h2 + (size_t)row_hi * 32 + col) =
                make_float2(acc[nb][2], acc[nb][3]);
    }
}

// ---------------- coefficients, layer 2 (thread per node) ----------------
__global__ void k_coef2(const float* __restrict__ as, const float* __restrict__ ad) {
    int n = blockIdx.x * blockDim.x + threadIdx.x;
    if (n >= NN) return;
    const float4* h4 = (const float4*)(g_h2 + (size_t)n * 32);
    float ps = 0.f, pd = 0.f;
#pragma unroll
    for (int j = 0; j < 8; j++) {
        float4 v = h4[j];
        float4 a = ((const float4*)as)[j];
        float4 b = ((const float4*)ad)[j];
        ps += v.x * a.x + v.y * a.y + v.z * a.z + v.w * a.w;
        pd += v.x * b.x + v.y * b.y + v.z * b.z + v.w * b.w;
    }
    g_e2s[n] = ps;
    g_e2d[n] = pd;
}

// ---------------- layer-2 CSR aggregate + finalize (warp per node) ----------------
__global__ void k_agg2c(float* __restrict__ out, const float* __restrict__ b2) {
    int node = (blockIdx.x * blockDim.x + threadIdx.x) >> 5;
    int lane = threadIdx.x & 31;
    if (node >= NN) return;
    int beg = g_rowptr[node], end = g_rowptr[node + 1];
    float ed = g_e2d[node];
    float acc = 0.f, ssum = 0.f;
    for (int i = beg; i < end; i++) {
        int s = g_csr[i];
        float p = __expf(lrelu(g_e2s[s] + ed));
        ssum += p;
        acc += p * g_h2[(size_t)s * 32 + lane];
    }
    out[(size_t)node * 32 + lane] = acc / (ssum + 1e-16f) + b2[lane];
}

// ---------------- launch ----------------
extern "C" void kernel_launch(void* const* d_in, const int* in_sizes, int n_in,
                              void* d_out, int out_size) {
    const float* x   = (const float*)d_in[0];
    const int*   ei  = (const int*)d_in[1];
    const float* W1  = (const float*)d_in[2];
    const float* as1 = (const float*)d_in[3];
    const float* ad1 = (const float*)d_in[4];
    const float* b1  = (const float*)d_in[5];
    const float* W2  = (const float*)d_in[6];
    const float* as2 = (const float*)d_in[7];
    const float* ad2 = (const float*)d_in[8];
    const float* b2  = (const float*)d_in[9];

    int Eo = in_sizes[1] / 2;
    if (Eo > EE) Eo = EE;
    int Et = Eo + NN;

    k_detect<<<1, 32>>>(ei);
    k_zero<<<(NN + 255) / 256, 256>>>();
    k_hist<<<(Et + 255) / 256, 256>>>(ei, Eo, Et);
    k_scan_a<<<NBLK, SCB>>>();
    k_scan_b<<<1, 128>>>();
    k_scan_c<<<NBLK, SCB>>>();
    k_fill<<<(Et + 255) / 256, 256>>>(ei, Eo, Et);

    k_cvtx<<<(NN * 128 / 8 + 255) / 256, 256>>>(x);
    k_cvtw<<<(128 * 256 / 8 + 63) / 64, 64>>>(W1);
    k_cvtw2<<<(256 * 32 / 8 + 63) / 64, 64>>>(W2);
    dim3 g1((NN + 127) / 128, C1 / 64);
    k_gemm1tc<<<g1, 256>>>();
    k_coef1<<<(NN * 32 + 255) / 256, 256>>>(as1, ad1);
    k_agg1c<<<(NN * 32 + 255) / 256, 256>>>(b1);

    k_gemm2tc<<<(NN + 127) / 128, 256>>>();
    k_coef2<<<(NN + 255) / 256, 256>>>(as2, ad2);
    k_agg2c<<<(NN * 32 + 255) / 256, 256>>>((float*)d_out, b2);
}